// round 1
// baseline (speedup 1.0000x reference)
#include <cuda_runtime.h>
#include <cstddef>

// Problem constants
static constexpr int B  = 4;
static constexpr int S  = 2048;
static constexpr int E  = 1024;
static constexpr int H  = 16;
static constexpr int D  = 64;       // E / H
static constexpr int BS = B * S;    // 8192 rows
static constexpr int BH = B * H;    // 64 batched heads

// ---------------------------------------------------------------------------
// Scratch (device globals; no dynamic allocation allowed)
// ---------------------------------------------------------------------------
__device__ float g_Q[(size_t)BH * S * D];          // [B,H,S,D]
__device__ float g_K[(size_t)BH * S * D];          // [B,H,S,D]
__device__ float g_V[(size_t)BH * S * D];          // [B,H,S,D]
__device__ float g_ctx[(size_t)BS * E];            // [B,S,E] (heads re-merged)
__device__ float g_scores[(size_t)BH * S * S];     // [B,H,S,S]  (1 GiB)

// ---------------------------------------------------------------------------
// Projection GEMM:  C[M,N] = A[M,K] @ W[N,K]^T + bias   (torch Linear)
// M=8192, N=K=1024. 128x128 tile, BK=8, 8x8 per thread, 256 threads.
// MODE 0/1/2: write Q/K/V in [B,H,S,D] layout.  MODE 3: A=g_ctx, plain
// row-major write to Cout (final output projection).
// ---------------------------------------------------------------------------
template <int MODE>
__global__ __launch_bounds__(256)
void proj_gemm(const float* __restrict__ Ain, const float* __restrict__ W,
               const float* __restrict__ bias, float* __restrict__ Cout)
{
    constexpr int K = E;
    constexpr int N = E;
    const float* A = (MODE == 3) ? (const float*)g_ctx : Ain;

    __shared__ float As[8][128];
    __shared__ float Bs[8][128];

    const int tid = threadIdx.x;
    const int tx  = tid & 15;          // 0..15 -> N direction
    const int ty  = tid >> 4;          // 0..15 -> M direction
    const int bm  = blockIdx.y;        // M tile (64 tiles)
    const int bn  = blockIdx.x;        // N tile (8 tiles)

    const float* Ablk = A + (size_t)bm * 128 * K;
    const float* Wblk = W + (size_t)bn * 128 * K;

    const int lrow = tid >> 1;         // 0..127
    const int lk4  = (tid & 1) * 4;    // 0 or 4

    float acc[8][8];
    #pragma unroll
    for (int i = 0; i < 8; i++)
        #pragma unroll
        for (int j = 0; j < 8; j++) acc[i][j] = 0.f;

    for (int k0 = 0; k0 < K; k0 += 8) {
        float4 a = *(const float4*)(Ablk + (size_t)lrow * K + k0 + lk4);
        float4 b = *(const float4*)(Wblk + (size_t)lrow * K + k0 + lk4);
        As[lk4 + 0][lrow] = a.x; As[lk4 + 1][lrow] = a.y;
        As[lk4 + 2][lrow] = a.z; As[lk4 + 3][lrow] = a.w;
        Bs[lk4 + 0][lrow] = b.x; Bs[lk4 + 1][lrow] = b.y;
        Bs[lk4 + 2][lrow] = b.z; Bs[lk4 + 3][lrow] = b.w;
        __syncthreads();

        #pragma unroll
        for (int k = 0; k < 8; k++) {
            float4 a0 = *(const float4*)&As[k][ty * 8];
            float4 a1 = *(const float4*)&As[k][ty * 8 + 4];
            float4 b0 = *(const float4*)&Bs[k][tx * 8];
            float4 b1 = *(const float4*)&Bs[k][tx * 8 + 4];
            float ra[8] = {a0.x, a0.y, a0.z, a0.w, a1.x, a1.y, a1.z, a1.w};
            float rb[8] = {b0.x, b0.y, b0.z, b0.w, b1.x, b1.y, b1.z, b1.w};
            #pragma unroll
            for (int i = 0; i < 8; i++)
                #pragma unroll
                for (int j = 0; j < 8; j++)
                    acc[i][j] = fmaf(ra[i], rb[j], acc[i][j]);
        }
        __syncthreads();
    }

    #pragma unroll
    for (int i = 0; i < 8; i++) {
        const int row = bm * 128 + ty * 8 + i;
        #pragma unroll
        for (int j = 0; j < 8; j++) {
            const int col = bn * 128 + tx * 8 + j;
            const float v = acc[i][j] + bias[col];
            if (MODE == 3) {
                Cout[(size_t)row * N + col] = v;
            } else {
                // scatter into [B,H,S,D]
                const int bb = row / S, ss = row - bb * S;
                const int hh = col / D, dd = col - hh * D;
                float* dst = (MODE == 0) ? g_Q : (MODE == 1) ? g_K : g_V;
                dst[(((size_t)(bb * H + hh)) * S + ss) * D + dd] = v;
            }
        }
    }
}

// ---------------------------------------------------------------------------
// Batched scores GEMM (NT): scores[z][q,k] = (1/8) * sum_d Q[z,q,d]*K[z,k,d]
// z = b*H+h, M=N=2048, Kd=64. Same 128x128x8 tile.
// ---------------------------------------------------------------------------
__global__ __launch_bounds__(256)
void scores_gemm()
{
    const int z = blockIdx.z;
    const float* A  = g_Q + (size_t)z * S * D;
    const float* Bm = g_K + (size_t)z * S * D;
    float* C        = g_scores + (size_t)z * S * S;

    __shared__ float As[8][128];
    __shared__ float Bs[8][128];

    const int tid = threadIdx.x;
    const int tx  = tid & 15;
    const int ty  = tid >> 4;
    const int bm  = blockIdx.y;        // 16 tiles
    const int bn  = blockIdx.x;        // 16 tiles

    const float* Ablk = A  + (size_t)bm * 128 * D;
    const float* Bblk = Bm + (size_t)bn * 128 * D;

    const int lrow = tid >> 1;
    const int lk4  = (tid & 1) * 4;

    float acc[8][8];
    #pragma unroll
    for (int i = 0; i < 8; i++)
        #pragma unroll
        for (int j = 0; j < 8; j++) acc[i][j] = 0.f;

    for (int k0 = 0; k0 < D; k0 += 8) {
        float4 a = *(const float4*)(Ablk + (size_t)lrow * D + k0 + lk4);
        float4 b = *(const float4*)(Bblk + (size_t)lrow * D + k0 + lk4);
        As[lk4 + 0][lrow] = a.x; As[lk4 + 1][lrow] = a.y;
        As[lk4 + 2][lrow] = a.z; As[lk4 + 3][lrow] = a.w;
        Bs[lk4 + 0][lrow] = b.x; Bs[lk4 + 1][lrow] = b.y;
        Bs[lk4 + 2][lrow] = b.z; Bs[lk4 + 3][lrow] = b.w;
        __syncthreads();

        #pragma unroll
        for (int k = 0; k < 8; k++) {
            float4 a0 = *(const float4*)&As[k][ty * 8];
            float4 a1 = *(const float4*)&As[k][ty * 8 + 4];
            float4 b0 = *(const float4*)&Bs[k][tx * 8];
            float4 b1 = *(const float4*)&Bs[k][tx * 8 + 4];
            float ra[8] = {a0.x, a0.y, a0.z, a0.w, a1.x, a1.y, a1.z, a1.w};
            float rb[8] = {b0.x, b0.y, b0.z, b0.w, b1.x, b1.y, b1.z, b1.w};
            #pragma unroll
            for (int i = 0; i < 8; i++)
                #pragma unroll
                for (int j = 0; j < 8; j++)
                    acc[i][j] = fmaf(ra[i], rb[j], acc[i][j]);
        }
        __syncthreads();
    }

    const float scale = 0.125f;   // 1/sqrt(64)
    #pragma unroll
    for (int i = 0; i < 8; i++) {
        const int row = bm * 128 + ty * 8 + i;
        #pragma unroll
        for (int j = 0; j < 8; j++) {
            const int col = bn * 128 + tx * 8 + j;
            C[(size_t)row * S + col] = acc[i][j] * scale;
        }
    }
}

// ---------------------------------------------------------------------------
// Row softmax in place over last dim (S=2048). One block (256 thr) per row.
// ---------------------------------------------------------------------------
__device__ __forceinline__ float warp_max(float v) {
    #pragma unroll
    for (int o = 16; o; o >>= 1) v = fmaxf(v, __shfl_xor_sync(0xffffffffu, v, o));
    return v;
}
__device__ __forceinline__ float warp_sum(float v) {
    #pragma unroll
    for (int o = 16; o; o >>= 1) v += __shfl_xor_sync(0xffffffffu, v, o);
    return v;
}

__global__ __launch_bounds__(256)
void softmax_kernel()
{
    const size_t row = blockIdx.x;            // 0 .. BH*S-1
    float* p = g_scores + row * S;
    const int tid = threadIdx.x;

    float4 v0 = ((const float4*)p)[tid];
    float4 v1 = ((const float4*)p)[tid + 256];

    float m = fmaxf(fmaxf(fmaxf(v0.x, v0.y), fmaxf(v0.z, v0.w)),
                    fmaxf(fmaxf(v1.x, v1.y), fmaxf(v1.z, v1.w)));

    __shared__ float red[8];
    m = warp_max(m);
    if ((tid & 31) == 0) red[tid >> 5] = m;
    __syncthreads();
    if (tid < 32) {
        float t = (tid < 8) ? red[tid] : -1e30f;
        t = warp_max(t);
        if (tid == 0) red[0] = t;
    }
    __syncthreads();
    m = red[0];

    v0.x = __expf(v0.x - m); v0.y = __expf(v0.y - m);
    v0.z = __expf(v0.z - m); v0.w = __expf(v0.w - m);
    v1.x = __expf(v1.x - m); v1.y = __expf(v1.y - m);
    v1.z = __expf(v1.z - m); v1.w = __expf(v1.w - m);

    float s = (v0.x + v0.y) + (v0.z + v0.w) + (v1.x + v1.y) + (v1.z + v1.w);
    s = warp_sum(s);
    __syncthreads();
    if ((tid & 31) == 0) red[tid >> 5] = s;
    __syncthreads();
    if (tid < 32) {
        float t = (tid < 8) ? red[tid] : 0.f;
        t = warp_sum(t);
        if (tid == 0) red[0] = t;
    }
    __syncthreads();
    const float inv = 1.0f / red[0];

    v0.x *= inv; v0.y *= inv; v0.z *= inv; v0.w *= inv;
    v1.x *= inv; v1.y *= inv; v1.z *= inv; v1.w *= inv;
    ((float4*)p)[tid]       = v0;
    ((float4*)p)[tid + 256] = v1;
}

// ---------------------------------------------------------------------------
// attn-mean over heads: out2[b,q,k] = (1/H) * sum_h attn[b,h,q,k]
// One block (256 thr) per (b,q) row.
// ---------------------------------------------------------------------------
__global__ __launch_bounds__(256)
void mean_kernel(float* __restrict__ out2)
{
    const int r = blockIdx.x;            // 0 .. BS-1
    const int b = r / S, q = r - b * S;
    const float* base = g_scores + (size_t)b * H * S * S + (size_t)q * S;
    float* o = out2 + (size_t)r * S;

    for (int k = threadIdx.x * 4; k < S; k += 256 * 4) {
        float4 acc = make_float4(0.f, 0.f, 0.f, 0.f);
        #pragma unroll
        for (int h = 0; h < H; h++) {
            float4 t = *(const float4*)(base + (size_t)h * S * S + k);
            acc.x += t.x; acc.y += t.y; acc.z += t.z; acc.w += t.w;
        }
        const float inv = 1.0f / (float)H;
        acc.x *= inv; acc.y *= inv; acc.z *= inv; acc.w *= inv;
        *(float4*)(o + k) = acc;
    }
}

// ---------------------------------------------------------------------------
// Context GEMM (NN): ctx[z][q,d] = sum_k attn[z][q,k] * V[z][k,d]
// M=2048, N=64, K=2048. 64x64 tile, BK=16, 4x4 per thread, 256 threads.
// Writes merged-head layout: g_ctx[(b*S+q)*E + h*D + d].
// ---------------------------------------------------------------------------
__global__ __launch_bounds__(256)
void ctx_gemm()
{
    const int z  = blockIdx.y;               // bh
    const int bm = blockIdx.x;               // 32 m-tiles of 64
    const float* A  = g_scores + (size_t)z * S * S;   // [2048,2048]
    const float* Bm = g_V      + (size_t)z * S * D;   // [2048,64]

    __shared__ float As[16][64];
    __shared__ float Bs[16][64];

    const int tid = threadIdx.x;
    const int tx  = tid & 15;          // N dir
    const int ty  = tid >> 4;          // M dir

    const int arow = tid >> 2;         // 0..63
    const int ak4  = (tid & 3) * 4;    // 0,4,8,12
    const int bk   = tid >> 4;         // 0..15
    const int bn4  = (tid & 15) * 4;   // 0..60

    float acc[4][4];
    #pragma unroll
    for (int i = 0; i < 4; i++)
        #pragma unroll
        for (int j = 0; j < 4; j++) acc[i][j] = 0.f;

    for (int k0 = 0; k0 < S; k0 += 16) {
        float4 a = *(const float4*)(A + (size_t)(bm * 64 + arow) * S + k0 + ak4);
        As[ak4 + 0][arow] = a.x; As[ak4 + 1][arow] = a.y;
        As[ak4 + 2][arow] = a.z; As[ak4 + 3][arow] = a.w;
        *(float4*)&Bs[bk][bn4] = *(const float4*)(Bm + (size_t)(k0 + bk) * D + bn4);
        __syncthreads();

        #pragma unroll
        for (int k = 0; k < 16; k++) {
            float4 ra4 = *(const float4*)&As[k][ty * 4];
            float4 rb4 = *(const float4*)&Bs[k][tx * 4];
            float ra[4] = {ra4.x, ra4.y, ra4.z, ra4.w};
            float rb[4] = {rb4.x, rb4.y, rb4.z, rb4.w};
            #pragma unroll
            for (int i = 0; i < 4; i++)
                #pragma unroll
                for (int j = 0; j < 4; j++)
                    acc[i][j] = fmaf(ra[i], rb[j], acc[i][j]);
        }
        __syncthreads();
    }

    const int b = z / H, h = z - b * H;
    #pragma unroll
    for (int i = 0; i < 4; i++) {
        const int q = bm * 64 + ty * 4 + i;
        #pragma unroll
        for (int j = 0; j < 4; j++) {
            const int d = tx * 4 + j;
            g_ctx[((size_t)(b * S + q)) * E + h * D + d] = acc[i][j];
        }
    }
}

// ---------------------------------------------------------------------------
// Launch
// ---------------------------------------------------------------------------
extern "C" void kernel_launch(void* const* d_in, const int* in_sizes, int n_in,
                              void* d_out, int out_size)
{
    const float* query = (const float*)d_in[0];
    const float* key   = (const float*)d_in[1];
    const float* value = (const float*)d_in[2];
    const float* Wq = (const float*)d_in[3];
    const float* bq = (const float*)d_in[4];
    const float* Wk = (const float*)d_in[5];
    const float* bk = (const float*)d_in[6];
    const float* Wv = (const float*)d_in[7];
    const float* bv = (const float*)d_in[8];
    const float* Wo = (const float*)d_in[9];
    const float* bo = (const float*)d_in[10];

    float* out       = (float*)d_out;                 // [B,S,E]
    float* attn_mean = out + (size_t)BS * E;          // [B,S,S]

    const dim3 projGrid(E / 128, BS / 128);           // (8, 64)
    proj_gemm<0><<<projGrid, 256>>>(query, Wq, bq, nullptr);
    proj_gemm<1><<<projGrid, 256>>>(key,   Wk, bk, nullptr);
    proj_gemm<2><<<projGrid, 256>>>(value, Wv, bv, nullptr);

    scores_gemm<<<dim3(S / 128, S / 128, BH), 256>>>();    // (16,16,64)

    softmax_kernel<<<(unsigned)((size_t)BH * S), 256>>>(); // 131072 rows

    mean_kernel<<<BS, 256>>>(attn_mean);

    ctx_gemm<<<dim3(S / 64, BH), 256>>>();                 // (32,64)

    proj_gemm<3><<<projGrid, 256>>>(nullptr, Wo, bo, out);
}

// round 3
// speedup vs baseline: 1.3567x; 1.3567x over previous
#include <cuda_runtime.h>
#include <cstddef>

// Problem constants
static constexpr int B  = 4;
static constexpr int S  = 2048;
static constexpr int E  = 1024;
static constexpr int H  = 16;
static constexpr int D  = 64;       // E / H
static constexpr int BS = B * S;    // 8192 rows
static constexpr int BH = B * H;    // 64 batched heads

// ---------------------------------------------------------------------------
// Scratch (device globals; no dynamic allocation allowed)
// ---------------------------------------------------------------------------
__device__ float g_Q[(size_t)BH * S * D];          // [B,H,S,D]
__device__ float g_K[(size_t)BH * S * D];          // [B,H,S,D]
__device__ float g_V[(size_t)BH * S * D];          // [B,H,S,D]
__device__ float g_ctx[(size_t)BS * E];            // [B,S,E] (heads re-merged)
__device__ float g_scores[(size_t)BH * S * S];     // [B,H,S,S]  (1 GiB)

// ---------------------------------------------------------------------------
// Projection GEMM:  C[M,N] = A[M,K] @ W[N,K]^T + bias   (torch Linear)
// M=8192, N=K=1024. 128x128 tile, BK=8 double-buffered, 8x8/thread, 256 thr.
// MODE 0/1/2: write Q/K/V in [B,H,S,D] layout.  MODE 3: A=g_ctx, row-major out.
// ---------------------------------------------------------------------------
template <int MODE>
__global__ __launch_bounds__(256)
void proj_gemm(const float* __restrict__ Ain, const float* __restrict__ W,
               const float* __restrict__ bias, float* __restrict__ Cout)
{
    constexpr int K = E;
    constexpr int N = E;
    constexpr int NT = K / 8;            // 128 k-tiles
    const float* A = (MODE == 3) ? (const float*)g_ctx : Ain;

    __shared__ float As[2][8][128];
    __shared__ float Bs[2][8][128];

    const int tid = threadIdx.x;
    const int tx  = tid & 15;
    const int ty  = tid >> 4;
    const int bm  = blockIdx.y;
    const int bn  = blockIdx.x;

    const int lrow = tid >> 1;           // 0..127
    const int lk4  = (tid & 1) * 4;      // 0 or 4

    const float* Aptr = A + (size_t)(bm * 128 + lrow) * K + lk4;
    const float* Wptr = W + (size_t)(bn * 128 + lrow) * K + lk4;

    float acc[8][8];
    #pragma unroll
    for (int i = 0; i < 8; i++)
        #pragma unroll
        for (int j = 0; j < 8; j++) acc[i][j] = 0.f;

    // prologue: tile 0
    {
        float4 a = *(const float4*)Aptr;
        float4 b = *(const float4*)Wptr;
        As[0][lk4 + 0][lrow] = a.x; As[0][lk4 + 1][lrow] = a.y;
        As[0][lk4 + 2][lrow] = a.z; As[0][lk4 + 3][lrow] = a.w;
        Bs[0][lk4 + 0][lrow] = b.x; Bs[0][lk4 + 1][lrow] = b.y;
        Bs[0][lk4 + 2][lrow] = b.z; Bs[0][lk4 + 3][lrow] = b.w;
    }
    __syncthreads();

    int buf = 0;
    for (int kt = 1; kt < NT; kt++) {
        float4 pa = *(const float4*)(Aptr + kt * 8);
        float4 pb = *(const float4*)(Wptr + kt * 8);

        #pragma unroll
        for (int k = 0; k < 8; k++) {
            float4 a0 = *(const float4*)&As[buf][k][ty * 8];
            float4 a1 = *(const float4*)&As[buf][k][ty * 8 + 4];
            float4 b0 = *(const float4*)&Bs[buf][k][tx * 8];
            float4 b1 = *(const float4*)&Bs[buf][k][tx * 8 + 4];
            float ra[8] = {a0.x, a0.y, a0.z, a0.w, a1.x, a1.y, a1.z, a1.w};
            float rb[8] = {b0.x, b0.y, b0.z, b0.w, b1.x, b1.y, b1.z, b1.w};
            #pragma unroll
            for (int i = 0; i < 8; i++)
                #pragma unroll
                for (int j = 0; j < 8; j++)
                    acc[i][j] = fmaf(ra[i], rb[j], acc[i][j]);
        }

        const int nb = buf ^ 1;
        As[nb][lk4 + 0][lrow] = pa.x; As[nb][lk4 + 1][lrow] = pa.y;
        As[nb][lk4 + 2][lrow] = pa.z; As[nb][lk4 + 3][lrow] = pa.w;
        Bs[nb][lk4 + 0][lrow] = pb.x; Bs[nb][lk4 + 1][lrow] = pb.y;
        Bs[nb][lk4 + 2][lrow] = pb.z; Bs[nb][lk4 + 3][lrow] = pb.w;
        __syncthreads();
        buf = nb;
    }
    // last tile
    #pragma unroll
    for (int k = 0; k < 8; k++) {
        float4 a0 = *(const float4*)&As[buf][k][ty * 8];
        float4 a1 = *(const float4*)&As[buf][k][ty * 8 + 4];
        float4 b0 = *(const float4*)&Bs[buf][k][tx * 8];
        float4 b1 = *(const float4*)&Bs[buf][k][tx * 8 + 4];
        float ra[8] = {a0.x, a0.y, a0.z, a0.w, a1.x, a1.y, a1.z, a1.w};
        float rb[8] = {b0.x, b0.y, b0.z, b0.w, b1.x, b1.y, b1.z, b1.w};
        #pragma unroll
        for (int i = 0; i < 8; i++)
            #pragma unroll
            for (int j = 0; j < 8; j++)
                acc[i][j] = fmaf(ra[i], rb[j], acc[i][j]);
    }

    #pragma unroll
    for (int i = 0; i < 8; i++) {
        const int row = bm * 128 + ty * 8 + i;
        #pragma unroll
        for (int j = 0; j < 8; j++) {
            const int col = bn * 128 + tx * 8 + j;
            const float v = acc[i][j] + bias[col];
            if (MODE == 3) {
                Cout[(size_t)row * N + col] = v;
            } else {
                const int bb = row / S, ss = row - bb * S;
                const int hh = col / D, dd = col - hh * D;
                float* dst = (MODE == 0) ? g_Q : (MODE == 1) ? g_K : g_V;
                dst[(((size_t)(bb * H + hh)) * S + ss) * D + dd] = v;
            }
        }
    }
}

// ---------------------------------------------------------------------------
// Batched scores GEMM (NT): scores[z][q,k] = sum_d (Q/8)[z,q,d]*K[z,k,d]
// Whole K=64 staged in shared once; sync-free 64-step FFMA loop.
// Dynamic smem: 64 KiB (Qs[64][128] + Ks[64][128]).
// ---------------------------------------------------------------------------
__global__ __launch_bounds__(256)
void scores_gemm()
{
    extern __shared__ float sm[];
    float (*Qs)[128] = (float (*)[128])sm;
    float (*Ks)[128] = (float (*)[128])(sm + 64 * 128);

    const int z  = blockIdx.z;
    const int bm = blockIdx.y;
    const int bn = blockIdx.x;
    const float* Aq = g_Q + (size_t)z * S * D;
    const float* Bk = g_K + (size_t)z * S * D;
    float* C        = g_scores + (size_t)z * S * S;

    const int tid  = threadIdx.x;
    const int tx   = tid & 15;
    const int ty   = tid >> 4;
    const int lrow = tid >> 1;
    const int lk4  = (tid & 1) * 4;

    const float* qp = Aq + (size_t)(bm * 128 + lrow) * D + lk4;
    const float* kp = Bk + (size_t)(bn * 128 + lrow) * D + lk4;

    #pragma unroll
    for (int i = 0; i < 8; i++) {
        float4 a = *(const float4*)(qp + i * 8);
        float4 b = *(const float4*)(kp + i * 8);
        const int kk = lk4 + i * 8;
        Qs[kk + 0][lrow] = a.x * 0.125f;   // fold 1/sqrt(D)
        Qs[kk + 1][lrow] = a.y * 0.125f;
        Qs[kk + 2][lrow] = a.z * 0.125f;
        Qs[kk + 3][lrow] = a.w * 0.125f;
        Ks[kk + 0][lrow] = b.x; Ks[kk + 1][lrow] = b.y;
        Ks[kk + 2][lrow] = b.z; Ks[kk + 3][lrow] = b.w;
    }
    __syncthreads();

    float acc[8][8];
    #pragma unroll
    for (int i = 0; i < 8; i++)
        #pragma unroll
        for (int j = 0; j < 8; j++) acc[i][j] = 0.f;

    #pragma unroll 16
    for (int k = 0; k < 64; k++) {
        float4 a0 = *(const float4*)&Qs[k][ty * 8];
        float4 a1 = *(const float4*)&Qs[k][ty * 8 + 4];
        float4 b0 = *(const float4*)&Ks[k][tx * 8];
        float4 b1 = *(const float4*)&Ks[k][tx * 8 + 4];
        float ra[8] = {a0.x, a0.y, a0.z, a0.w, a1.x, a1.y, a1.z, a1.w};
        float rb[8] = {b0.x, b0.y, b0.z, b0.w, b1.x, b1.y, b1.z, b1.w};
        #pragma unroll
        for (int i = 0; i < 8; i++)
            #pragma unroll
            for (int j = 0; j < 8; j++)
                acc[i][j] = fmaf(ra[i], rb[j], acc[i][j]);
    }

    #pragma unroll
    for (int i = 0; i < 8; i++) {
        const int row = bm * 128 + ty * 8 + i;
        float* cp = C + (size_t)row * S + bn * 128 + tx * 8;
        *(float4*)cp       = make_float4(acc[i][0], acc[i][1], acc[i][2], acc[i][3]);
        *(float4*)(cp + 4) = make_float4(acc[i][4], acc[i][5], acc[i][6], acc[i][7]);
    }
}

// ---------------------------------------------------------------------------
// Fused softmax (in place) + mean-over-heads.
// One block (256 thr) per (b,q); iterates the 16 head rows; head-mean kept
// in registers (each thread owns 8 fixed columns).
// ---------------------------------------------------------------------------
__device__ __forceinline__ float warp_max(float v) {
    #pragma unroll
    for (int o = 16; o; o >>= 1) v = fmaxf(v, __shfl_xor_sync(0xffffffffu, v, o));
    return v;
}
__device__ __forceinline__ float warp_sum(float v) {
    #pragma unroll
    for (int o = 16; o; o >>= 1) v += __shfl_xor_sync(0xffffffffu, v, o);
    return v;
}

__global__ __launch_bounds__(256)
void softmax_mean_kernel(float* __restrict__ out2)
{
    const int r = blockIdx.x;                  // 0..BS-1
    const int b = r >> 11, q = r & (S - 1);
    const int tid = threadIdx.x;

    __shared__ float redm[8];
    __shared__ float reds[8];

    float4 m0 = make_float4(0.f, 0.f, 0.f, 0.f);
    float4 m1 = make_float4(0.f, 0.f, 0.f, 0.f);

    for (int h = 0; h < H; h++) {
        float* p = g_scores + (((size_t)(b * H + h)) * S + q) * S;
        float4 v0 = ((const float4*)p)[tid];
        float4 v1 = ((const float4*)p)[tid + 256];

        float m = fmaxf(fmaxf(fmaxf(v0.x, v0.y), fmaxf(v0.z, v0.w)),
                        fmaxf(fmaxf(v1.x, v1.y), fmaxf(v1.z, v1.w)));
        m = warp_max(m);
        if ((tid & 31) == 0) redm[tid >> 5] = m;
        __syncthreads();
        if (tid < 32) {
            float t = (tid < 8) ? redm[tid] : -1e30f;
            t = warp_max(t);
            if (tid == 0) redm[0] = t;
        }
        __syncthreads();
        m = redm[0];

        v0.x = __expf(v0.x - m); v0.y = __expf(v0.y - m);
        v0.z = __expf(v0.z - m); v0.w = __expf(v0.w - m);
        v1.x = __expf(v1.x - m); v1.y = __expf(v1.y - m);
        v1.z = __expf(v1.z - m); v1.w = __expf(v1.w - m);

        float s = (v0.x + v0.y) + (v0.z + v0.w) + (v1.x + v1.y) + (v1.z + v1.w);
        s = warp_sum(s);
        if ((tid & 31) == 0) reds[tid >> 5] = s;
        __syncthreads();
        if (tid < 32) {
            float t = (tid < 8) ? reds[tid] : 0.f;
            t = warp_sum(t);
            if (tid == 0) reds[0] = t;
        }
        __syncthreads();
        const float inv = 1.0f / reds[0];
        __syncthreads();   // everyone consumed reds[0]/redm before next head reuses

        v0.x *= inv; v0.y *= inv; v0.z *= inv; v0.w *= inv;
        v1.x *= inv; v1.y *= inv; v1.z *= inv; v1.w *= inv;
        ((float4*)p)[tid]       = v0;
        ((float4*)p)[tid + 256] = v1;

        m0.x += v0.x; m0.y += v0.y; m0.z += v0.z; m0.w += v0.w;
        m1.x += v1.x; m1.y += v1.y; m1.z += v1.z; m1.w += v1.w;
    }

    const float invH = 1.0f / (float)H;
    m0.x *= invH; m0.y *= invH; m0.z *= invH; m0.w *= invH;
    m1.x *= invH; m1.y *= invH; m1.z *= invH; m1.w *= invH;
    float* o = out2 + (size_t)r * S;
    ((float4*)o)[tid]       = m0;
    ((float4*)o)[tid + 256] = m1;
}

// ---------------------------------------------------------------------------
// Context GEMM (NN): ctx[z][q,d] = sum_k attn[z][q,k] * V[z][k,d]
// M=2048, N=64, K=2048. 128x64 tile, BK=16 double-buffered, 8x4/thread.
// Writes merged-head layout g_ctx[(b*S+q)*E + h*D + d].
// ---------------------------------------------------------------------------
__global__ __launch_bounds__(256)
void ctx_gemm()
{
    const int z  = blockIdx.y;
    const int bm = blockIdx.x;                       // 16 m-tiles of 128
    const float* A  = g_scores + (size_t)z * S * S;  // [2048,2048]
    const float* Bm = g_V      + (size_t)z * S * D;  // [2048,64]

    __shared__ float As[2][16][128];
    __shared__ float Bs[2][16][64];

    const int tid = threadIdx.x;
    const int tx  = tid & 15;            // 4 cols each -> 64
    const int ty  = tid >> 4;            // 8 rows each -> 128

    const int arow = tid >> 1;           // 0..127
    const int ak   = (tid & 1) * 8;      // 0 or 8 (two float4: +0,+4)
    const int brow = tid >> 4;           // 0..15
    const int bcol = (tid & 15) * 4;     // 0..60

    const float* Aptr = A  + (size_t)(bm * 128 + arow) * S + ak;
    const float* Bptr = Bm + (size_t)brow * D + bcol;

    float acc[8][4];
    #pragma unroll
    for (int i = 0; i < 8; i++)
        #pragma unroll
        for (int j = 0; j < 4; j++) acc[i][j] = 0.f;

    // prologue
    {
        float4 a0 = *(const float4*)Aptr;
        float4 a1 = *(const float4*)(Aptr + 4);
        float4 bb = *(const float4*)Bptr;
        As[0][ak + 0][arow] = a0.x; As[0][ak + 1][arow] = a0.y;
        As[0][ak + 2][arow] = a0.z; As[0][ak + 3][arow] = a0.w;
        As[0][ak + 4][arow] = a1.x; As[0][ak + 5][arow] = a1.y;
        As[0][ak + 6][arow] = a1.z; As[0][ak + 7][arow] = a1.w;
        *(float4*)&Bs[0][brow][bcol] = bb;
    }
    __syncthreads();

    int buf = 0;
    constexpr int NT = S / 16;           // 128
    for (int kt = 1; kt < NT; kt++) {
        float4 a0 = *(const float4*)(Aptr + kt * 16);
        float4 a1 = *(const float4*)(Aptr + kt * 16 + 4);
        float4 bb = *(const float4*)(Bptr + (size_t)kt * 16 * D);

        #pragma unroll
        for (int k = 0; k < 16; k++) {
            float4 ra0 = *(const float4*)&As[buf][k][ty * 8];
            float4 ra1 = *(const float4*)&As[buf][k][ty * 8 + 4];
            float4 rb4 = *(const float4*)&Bs[buf][k][tx * 4];
            float ra[8] = {ra0.x, ra0.y, ra0.z, ra0.w, ra1.x, ra1.y, ra1.z, ra1.w};
            float rb[4] = {rb4.x, rb4.y, rb4.z, rb4.w};
            #pragma unroll
            for (int i = 0; i < 8; i++)
                #pragma unroll
                for (int j = 0; j < 4; j++)
                    acc[i][j] = fmaf(ra[i], rb[j], acc[i][j]);
        }

        const int nb = buf ^ 1;
        As[nb][ak + 0][arow] = a0.x; As[nb][ak + 1][arow] = a0.y;
        As[nb][ak + 2][arow] = a0.z; As[nb][ak + 3][arow] = a0.w;
        As[nb][ak + 4][arow] = a1.x; As[nb][ak + 5][arow] = a1.y;
        As[nb][ak + 6][arow] = a1.z; As[nb][ak + 7][arow] = a1.w;
        *(float4*)&Bs[nb][brow][bcol] = bb;
        __syncthreads();
        buf = nb;
    }
    #pragma unroll
    for (int k = 0; k < 16; k++) {
        float4 ra0 = *(const float4*)&As[buf][k][ty * 8];
        float4 ra1 = *(const float4*)&As[buf][k][ty * 8 + 4];
        float4 rb4 = *(const float4*)&Bs[buf][k][tx * 4];
        float ra[8] = {ra0.x, ra0.y, ra0.z, ra0.w, ra1.x, ra1.y, ra1.z, ra1.w};
        float rb[4] = {rb4.x, rb4.y, rb4.z, rb4.w};
        #pragma unroll
        for (int i = 0; i < 8; i++)
            #pragma unroll
            for (int j = 0; j < 4; j++)
                acc[i][j] = fmaf(ra[i], rb[j], acc[i][j]);
    }

    const int b = z / H, h = z - b * H;
    #pragma unroll
    for (int i = 0; i < 8; i++) {
        const int qq = bm * 128 + ty * 8 + i;
        float* cp = g_ctx + ((size_t)(b * S + qq)) * E + h * D + tx * 4;
        *(float4*)cp = make_float4(acc[i][0], acc[i][1], acc[i][2], acc[i][3]);
    }
}

// ---------------------------------------------------------------------------
// Launch
// ---------------------------------------------------------------------------
extern "C" void kernel_launch(void* const* d_in, const int* in_sizes, int n_in,
                              void* d_out, int out_size)
{
    const float* query = (const float*)d_in[0];
    const float* key   = (const float*)d_in[1];
    const float* value = (const float*)d_in[2];
    const float* Wq = (const float*)d_in[3];
    const float* bq = (const float*)d_in[4];
    const float* Wk = (const float*)d_in[5];
    const float* bk = (const float*)d_in[6];
    const float* Wv = (const float*)d_in[7];
    const float* bv = (const float*)d_in[8];
    const float* Wo = (const float*)d_in[9];
    const float* bo = (const float*)d_in[10];

    float* out       = (float*)d_out;                 // [B,S,E]
    float* attn_mean = out + (size_t)BS * E;          // [B,S,S]

    const int scoresSmem = 2 * 64 * 128 * (int)sizeof(float);  // 64 KiB
    cudaFuncSetAttribute(scores_gemm,
                         cudaFuncAttributeMaxDynamicSharedMemorySize, scoresSmem);

    const dim3 projGrid(E / 128, BS / 128);           // (8, 64)
    proj_gemm<0><<<projGrid, 256>>>(query, Wq, bq, nullptr);
    proj_gemm<1><<<projGrid, 256>>>(key,   Wk, bk, nullptr);
    proj_gemm<2><<<projGrid, 256>>>(value, Wv, bv, nullptr);

    scores_gemm<<<dim3(S / 128, S / 128, BH), 256, scoresSmem>>>();  // (16,16,64)

    softmax_mean_kernel<<<BS, 256>>>(attn_mean);      // 8192 blocks

    ctx_gemm<<<dim3(S / 128, BH), 256>>>();           // (16,64)

    proj_gemm<3><<<projGrid, 256>>>(nullptr, Wo, bo, out);
}

// round 8
// speedup vs baseline: 2.7443x; 2.0228x over previous
#include <cuda_runtime.h>
#include <cuda_bf16.h>
#include <cstdint>
#include <cstddef>

// Problem constants
static constexpr int B  = 4;
static constexpr int S  = 2048;
static constexpr int E  = 1024;
static constexpr int H  = 16;
static constexpr int D  = 64;
static constexpr int BS = B * S;    // 8192
static constexpr int BH = B * H;    // 64

// ---------------------------------------------------------------------------
// Scratch
// ---------------------------------------------------------------------------
__device__ float g_Q     [(size_t)BH * S * D];   // [z,s,d] (pre-scaled by 1/8)
__device__ float g_K     [(size_t)BH * S * D];   // [z,s,d]
__device__ float g_Vt    [(size_t)BH * D * S];   // [z,d,s]
__device__ float g_ctx   [(size_t)BS * E];       // [b,s,e]
__device__ float g_expS  [(size_t)BH * S * S];   // [z,q,k] unnormalized exp
__device__ float g_psum  [(size_t)BH * S * 32];  // [z,q,32] row partial sums
__device__ float g_rowinv[(size_t)BH * S];       // [z,q] 1/rowsum

// ---------------------------------------------------------------------------
// Helpers
// ---------------------------------------------------------------------------
__device__ __forceinline__ uint32_t smem_u32(const void* p) {
    uint32_t a;
    asm("{ .reg .u64 t; cvta.to.shared.u64 t, %1; cvt.u32.u64 %0, t; }" : "=r"(a) : "l"(p));
    return a;
}
// pack two fp32 -> bf16x2, e0 in low half
__device__ __forceinline__ uint32_t cvt2(float e0, float e1) {
    uint32_t r;
    asm("cvt.rn.bf16x2.f32 %0, %1, %2;" : "=r"(r) : "f"(e1), "f"(e0));
    return r;
}
__device__ __forceinline__ void pack_hilo(float4 v, uint2& hi, uint2& lo) {
    uint32_t h01 = cvt2(v.x, v.y);
    uint32_t h23 = cvt2(v.z, v.w);
    float hf0 = __uint_as_float(h01 << 16), hf1 = __uint_as_float(h01 & 0xFFFF0000u);
    float hf2 = __uint_as_float(h23 << 16), hf3 = __uint_as_float(h23 & 0xFFFF0000u);
    lo = make_uint2(cvt2(v.x - hf0, v.y - hf1), cvt2(v.z - hf2, v.w - hf3));
    hi = make_uint2(h01, h23);
}
#define LDSM_X4(r0, r1, r2, r3, addr) \
    asm volatile("ldmatrix.sync.aligned.m8n8.x4.shared.b16 {%0,%1,%2,%3}, [%4];" \
        : "=r"(r0), "=r"(r1), "=r"(r2), "=r"(r3) : "r"(addr))

__device__ __forceinline__ void mma_bf16(float* d, const uint32_t* a, const uint32_t* b) {
    asm volatile(
        "mma.sync.aligned.m16n8k16.row.col.f32.bf16.bf16.f32 "
        "{%0,%1,%2,%3}, {%4,%5,%6,%7}, {%8,%9}, {%0,%1,%2,%3};"
        : "+f"(d[0]), "+f"(d[1]), "+f"(d[2]), "+f"(d[3])
        : "r"(a[0]), "r"(a[1]), "r"(a[2]), "r"(a[3]), "r"(b[0]), "r"(b[1]));
}

// ---------------------------------------------------------------------------
// Generic bf16x3 mma.sync GEMM.  C = A[M,K] @ Bmat[N,K]^T (both k-major).
// CTA tile: 128 x NTILE.  8 warps as (4 m) x (2 n); warp tile 32 x NTILE/2.
// MODE 0/1/2: Q/K/V projection.  MODE 3: O projection.
// MODE 4: scores + exp + partial rowsums.  MODE 5: ctx (normalized attn @ V).
// ---------------------------------------------------------------------------
static constexpr int A_SZ = 128 * 80;       // one A buffer (hi or lo), 80B rows
static constexpr int SM_TOTAL = 4 * A_SZ + 4 * (128 * 80);  // 81920

template <int MODE>
__global__ __launch_bounds__(256, 1)
void mm_gemm(const float* __restrict__ Ain, const float* __restrict__ Bin,
             const float* __restrict__ bias, float* __restrict__ Cout)
{
    constexpr int NTILE = (MODE == 5) ? 64 : 128;
    constexpr int NC    = (MODE == 4) ? 2 : (MODE == 5) ? 64 : 32;  // k chunks of 32
    constexpr int LDA   = (MODE == 4) ? 64 : (MODE == 5) ? 2048 : 1024;
    constexpr int LDB   = (MODE == 4) ? 64 : (MODE == 5) ? 2048 : 1024;
    constexpr int WN    = NTILE / 2;       // warp n extent
    constexpr int NF    = WN / 8;          // n fragments per warp (8 or 4)
    constexpr int B_SZ  = NTILE * 80;
    constexpr int OFFB0 = 4 * A_SZ;

    extern __shared__ char smem[];
    const uint32_t sb = smem_u32(smem);
    const int tid = threadIdx.x, wid = tid >> 5, l = tid & 31;
    const int wm = wid >> 1, wn = wid & 1;
    const int bn = blockIdx.x, bm = blockIdx.y;
    const int z  = (MODE >= 4) ? blockIdx.z : 0;

    const float* Abase;
    const float* Bbase;
    if constexpr (MODE == 4)      { Abase = g_Q    + (size_t)z * S * D; Bbase = g_K  + (size_t)z * S * D; }
    else if constexpr (MODE == 5) { Abase = g_expS + (size_t)z * S * S; Bbase = g_Vt + (size_t)z * D * S; }
    else if constexpr (MODE == 3) { Abase = g_ctx;                      Bbase = Bin; }
    else                          { Abase = Ain;                        Bbase = Bin; }

    // global load mapping
    const int arow = tid >> 1, acol = (tid & 1) * 16;
    const int browL = (NTILE == 128) ? (tid >> 1) : (tid >> 2);
    const int bcolL = (NTILE == 128) ? (tid & 1) * 16 : (tid & 3) * 8;
    constexpr int NBL = (NTILE == 128) ? 4 : 2;

    const float* aG = Abase + (size_t)(bm * 128 + arow) * LDA + acol;
    const float* bG = Bbase + (size_t)(bn * NTILE + browL) * LDB + bcolL;

    // ldmatrix per-lane selectors
    const int aRowSel = ((l >> 3) & 1) * 8 + (l & 7);
    const int aKsel   = ((l >> 4) & 1) * 16;
    const int bRowSel = ((l >> 4) & 1) * 8 + (l & 7);
    const int bKsel   = ((l >> 3) & 1) * 16;

    float dacc[2][NF][4];
    #pragma unroll
    for (int mf = 0; mf < 2; mf++)
        #pragma unroll
        for (int nf = 0; nf < NF; nf++)
            #pragma unroll
            for (int u = 0; u < 4; u++) dacc[mf][nf][u] = 0.f;

    float4 aR[4], bR[NBL];
    #pragma unroll
    for (int i = 0; i < 4;  i++) aR[i] = *(const float4*)(aG + 4 * i);
    #pragma unroll
    for (int i = 0; i < NBL; i++) bR[i] = *(const float4*)(bG + 4 * i);

    // stage chunk 0
    {
        #pragma unroll
        for (int i = 0; i < 4; i++) {
            uint2 hi, lo; pack_hilo(aR[i], hi, lo);
            const int off = arow * 80 + (acol + 4 * i) * 2;
            *(uint2*)(smem + off)        = hi;
            *(uint2*)(smem + A_SZ + off) = lo;
        }
        #pragma unroll
        for (int i = 0; i < NBL; i++) {
            uint2 hi, lo; pack_hilo(bR[i], hi, lo);
            const int off = browL * 80 + (bcolL + 4 * i) * 2;
            *(uint2*)(smem + OFFB0 + off)        = hi;
            *(uint2*)(smem + OFFB0 + B_SZ + off) = lo;
        }
    }
    __syncthreads();

    for (int c = 0; c < NC; c++) {
        const int buf = c & 1;
        if (c + 1 < NC) {
            #pragma unroll
            for (int i = 0; i < 4;  i++) aR[i] = *(const float4*)(aG + (c + 1) * 32 + 4 * i);
            #pragma unroll
            for (int i = 0; i < NBL; i++) bR[i] = *(const float4*)(bG + (c + 1) * 32 + 4 * i);
        }

        const uint32_t aB = sb + buf * 2 * A_SZ;
        const uint32_t bB = sb + OFFB0 + buf * 2 * B_SZ;

        #pragma unroll
        for (int s = 0; s < 2; s++) {
            uint32_t af[2][2][4];                 // [mf][hi/lo][4]
            #pragma unroll
            for (int mf = 0; mf < 2; mf++)
                #pragma unroll
                for (int hl = 0; hl < 2; hl++) {
                    const uint32_t ad = aB + hl * A_SZ +
                        (wm * 32 + mf * 16 + aRowSel) * 80 + s * 32 + aKsel;
                    LDSM_X4(af[mf][hl][0], af[mf][hl][1], af[mf][hl][2], af[mf][hl][3], ad);
                }
            uint32_t bf[NF][2][2];                // [nf][hi/lo][2]
            #pragma unroll
            for (int np = 0; np < NF / 2; np++)
                #pragma unroll
                for (int hl = 0; hl < 2; hl++) {
                    uint32_t r0, r1, r2, r3;
                    const uint32_t bd = bB + hl * B_SZ +
                        (wn * WN + np * 16 + bRowSel) * 80 + s * 32 + bKsel;
                    LDSM_X4(r0, r1, r2, r3, bd);
                    bf[2 * np][hl][0] = r0; bf[2 * np][hl][1] = r1;
                    bf[2 * np + 1][hl][0] = r2; bf[2 * np + 1][hl][1] = r3;
                }
            #pragma unroll
            for (int mf = 0; mf < 2; mf++)
                #pragma unroll
                for (int nf = 0; nf < NF; nf++) {
                    mma_bf16(dacc[mf][nf], af[mf][0], bf[nf][0]);   // hi*hi
                    mma_bf16(dacc[mf][nf], af[mf][1], bf[nf][0]);   // lo*hi
                    mma_bf16(dacc[mf][nf], af[mf][0], bf[nf][1]);   // hi*lo
                }
        }

        if (c + 1 < NC) {
            __syncthreads();
            const int nb = (c + 1) & 1;
            #pragma unroll
            for (int i = 0; i < 4; i++) {
                uint2 hi, lo; pack_hilo(aR[i], hi, lo);
                const int off = nb * 2 * A_SZ + arow * 80 + (acol + 4 * i) * 2;
                *(uint2*)(smem + off)        = hi;
                *(uint2*)(smem + A_SZ + off) = lo;
            }
            #pragma unroll
            for (int i = 0; i < NBL; i++) {
                uint2 hi, lo; pack_hilo(bR[i], hi, lo);
                const int off = OFFB0 + nb * 2 * B_SZ + browL * 80 + (bcolL + 4 * i) * 2;
                *(uint2*)(smem + off)        = hi;
                *(uint2*)(smem + B_SZ + off) = lo;
            }
            __syncthreads();
        }
    }

    // ------------------------- epilogue -------------------------
    const int g = l >> 2;                 // row group within fragment
    const int cq = (l & 3) * 2;           // col pair within fragment

    #pragma unroll
    for (int mf = 0; mf < 2; mf++) {
        const int row0 = bm * 128 + wm * 32 + mf * 16 + g;
        const int row1 = row0 + 8;
        float rs0 = 0.f, rs1 = 0.f;
        float inv0 = 1.f, inv1 = 1.f;
        if constexpr (MODE == 5) {
            inv0 = g_rowinv[(size_t)z * S + row0];
            inv1 = g_rowinv[(size_t)z * S + row1];
        }
        #pragma unroll
        for (int nf = 0; nf < NF; nf++) {
            const int gcol = bn * NTILE + wn * WN + nf * 8 + cq;
            float v0 = dacc[mf][nf][0], v1 = dacc[mf][nf][1];
            float v2 = dacc[mf][nf][2], v3 = dacc[mf][nf][3];

            if constexpr (MODE <= 2) {
                const float b0 = __ldg(bias + gcol), b1 = __ldg(bias + gcol + 1);
                v0 += b0; v1 += b1; v2 += b0; v3 += b1;
                if (MODE == 0) { v0 *= 0.125f; v1 *= 0.125f; v2 *= 0.125f; v3 *= 0.125f; }
                const int hh = gcol >> 6, dd = gcol & 63;
                const int bb0 = row0 >> 11, ss0 = row0 & (S - 1);
                const int bb1 = row1 >> 11, ss1 = row1 & (S - 1);
                if constexpr (MODE == 0) {
                    *(float2*)(g_Q + (((size_t)(bb0 * H + hh)) * S + ss0) * D + dd) = make_float2(v0, v1);
                    *(float2*)(g_Q + (((size_t)(bb1 * H + hh)) * S + ss1) * D + dd) = make_float2(v2, v3);
                } else if constexpr (MODE == 1) {
                    *(float2*)(g_K + (((size_t)(bb0 * H + hh)) * S + ss0) * D + dd) = make_float2(v0, v1);
                    *(float2*)(g_K + (((size_t)(bb1 * H + hh)) * S + ss1) * D + dd) = make_float2(v2, v3);
                } else {
                    float* vt0 = g_Vt + (((size_t)(bb0 * H + hh)) * D + dd) * S + ss0;
                    float* vt1 = g_Vt + (((size_t)(bb1 * H + hh)) * D + dd) * S + ss1;
                    vt0[0] = v0; vt0[S] = v1;
                    vt1[0] = v2; vt1[S] = v3;
                }
            } else if constexpr (MODE == 3) {
                const float b0 = __ldg(bias + gcol), b1 = __ldg(bias + gcol + 1);
                *(float2*)(Cout + (size_t)row0 * E + gcol) = make_float2(v0 + b0, v1 + b1);
                *(float2*)(Cout + (size_t)row1 * E + gcol) = make_float2(v2 + b0, v3 + b1);
            } else if constexpr (MODE == 4) {
                const float e0 = __expf(v0), e1 = __expf(v1);
                const float e2 = __expf(v2), e3 = __expf(v3);
                rs0 += e0 + e1; rs1 += e2 + e3;
                *(float2*)(g_expS + ((size_t)z * S + row0) * S + gcol) = make_float2(e0, e1);
                *(float2*)(g_expS + ((size_t)z * S + row1) * S + gcol) = make_float2(e2, e3);
            } else {  // MODE 5
                const int bb = z >> 4, hh = z & (H - 1);
                const int dd = wn * WN + nf * 8 + cq;   // N = 64 = D
                *(float2*)(g_ctx + ((size_t)(bb * S + row0)) * E + hh * D + dd) =
                    make_float2(v0 * inv0, v1 * inv0);
                *(float2*)(g_ctx + ((size_t)(bb * S + row1)) * E + hh * D + dd) =
                    make_float2(v2 * inv1, v3 * inv1);
            }
        }
        if constexpr (MODE == 4) {
            rs0 += __shfl_xor_sync(0xffffffffu, rs0, 1);
            rs0 += __shfl_xor_sync(0xffffffffu, rs0, 2);
            rs1 += __shfl_xor_sync(0xffffffffu, rs1, 1);
            rs1 += __shfl_xor_sync(0xffffffffu, rs1, 2);
            if ((l & 3) == 0) {
                const int slot = bn * 2 + wn;
                g_psum[((size_t)z * S + row0) * 32 + slot] = rs0;
                g_psum[((size_t)z * S + row1) * 32 + slot] = rs1;
            }
        }
    }
}

// ---------------------------------------------------------------------------
// mean over heads + rowinv: out2[b,q,k] = sum_h expS[b,h,q,k]/(rowsum_h * H)
// ---------------------------------------------------------------------------
__global__ __launch_bounds__(256)
void mean_kernel(float* __restrict__ out2)
{
    const int r = blockIdx.x;                  // 0..BS-1
    const int b = r >> 11, q = r & (S - 1);
    const int tid = threadIdx.x;

    __shared__ float inv[H];
    if (tid < H) {
        const float4* ps = (const float4*)(g_psum + ((size_t)(b * H + tid) * S + q) * 32);
        float s = 0.f;
        #pragma unroll
        for (int i = 0; i < 8; i++) {
            float4 t = ps[i];
            s += (t.x + t.y) + (t.z + t.w);
        }
        const float ri = 1.0f / s;
        g_rowinv[(size_t)(b * H + tid) * S + q] = ri;
        inv[tid] = ri * (1.0f / (float)H);
    }
    __syncthreads();

    float4 a0 = make_float4(0.f, 0.f, 0.f, 0.f);
    float4 a1 = make_float4(0.f, 0.f, 0.f, 0.f);
    #pragma unroll
    for (int h = 0; h < H; h++) {
        const float4* p = (const float4*)(g_expS + ((size_t)(b * H + h) * S + q) * S);
        const float iv = inv[h];
        float4 t0 = p[tid], t1 = p[tid + 256];
        a0.x += t0.x * iv; a0.y += t0.y * iv; a0.z += t0.z * iv; a0.w += t0.w * iv;
        a1.x += t1.x * iv; a1.y += t1.y * iv; a1.z += t1.z * iv; a1.w += t1.w * iv;
    }
    float* o = out2 + (size_t)r * S;
    ((float4*)o)[tid]       = a0;
    ((float4*)o)[tid + 256] = a1;
}

// ---------------------------------------------------------------------------
// Launch
// ---------------------------------------------------------------------------
extern "C" void kernel_launch(void* const* d_in, const int* in_sizes, int n_in,
                              void* d_out, int out_size)
{
    const float* query = (const float*)d_in[0];
    const float* key   = (const float*)d_in[1];
    const float* value = (const float*)d_in[2];
    const float* Wq = (const float*)d_in[3];
    const float* bq = (const float*)d_in[4];
    const float* Wk = (const float*)d_in[5];
    const float* bk = (const float*)d_in[6];
    const float* Wv = (const float*)d_in[7];
    const float* bv = (const float*)d_in[8];
    const float* Wo = (const float*)d_in[9];
    const float* bo = (const float*)d_in[10];

    float* out       = (float*)d_out;
    float* attn_mean = out + (size_t)BS * E;

    cudaFuncSetAttribute(mm_gemm<0>, cudaFuncAttributeMaxDynamicSharedMemorySize, SM_TOTAL);
    cudaFuncSetAttribute(mm_gemm<1>, cudaFuncAttributeMaxDynamicSharedMemorySize, SM_TOTAL);
    cudaFuncSetAttribute(mm_gemm<2>, cudaFuncAttributeMaxDynamicSharedMemorySize, SM_TOTAL);
    cudaFuncSetAttribute(mm_gemm<3>, cudaFuncAttributeMaxDynamicSharedMemorySize, SM_TOTAL);
    cudaFuncSetAttribute(mm_gemm<4>, cudaFuncAttributeMaxDynamicSharedMemorySize, SM_TOTAL);
    cudaFuncSetAttribute(mm_gemm<5>, cudaFuncAttributeMaxDynamicSharedMemorySize, SM_TOTAL);

    const dim3 projGrid(E / 128, BS / 128);                 // (8, 64)
    mm_gemm<0><<<projGrid, 256, SM_TOTAL>>>(query, Wq, bq, nullptr);
    mm_gemm<1><<<projGrid, 256, SM_TOTAL>>>(key,   Wk, bk, nullptr);
    mm_gemm<2><<<projGrid, 256, SM_TOTAL>>>(value, Wv, bv, nullptr);

    mm_gemm<4><<<dim3(S / 128, S / 128, BH), 256, SM_TOTAL>>>(nullptr, nullptr, nullptr, nullptr);

    mean_kernel<<<BS, 256>>>(attn_mean);

    mm_gemm<5><<<dim3(1, S / 128, BH), 256, SM_TOTAL>>>(nullptr, nullptr, nullptr, nullptr);

    mm_gemm<3><<<projGrid, 256, SM_TOTAL>>>(nullptr, Wo, bo, out);
}

// round 12
// speedup vs baseline: 2.9498x; 1.0749x over previous
#include <cuda_runtime.h>
#include <cuda_bf16.h>
#include <cuda_fp16.h>
#include <cstdint>
#include <cstddef>

// Problem constants
static constexpr int B  = 4;
static constexpr int S  = 2048;
static constexpr int E  = 1024;
static constexpr int H  = 16;
static constexpr int D  = 64;
static constexpr int BS = B * S;    // 8192
static constexpr int BH = B * H;    // 64

// ---------------------------------------------------------------------------
// Scratch
// ---------------------------------------------------------------------------
__device__ float  g_Q     [(size_t)BH * S * D];   // [z,s,d] (pre-scaled by 1/8)
__device__ float  g_K     [(size_t)BH * S * D];   // [z,s,d]
__device__ float  g_Vt    [(size_t)BH * D * S];   // [z,d,s]
__device__ float  g_ctx   [(size_t)BS * E];       // [b,s,e]
__device__ __half g_expS  [(size_t)BH * S * S];   // [z,q,k] unnormalized exp (fp16)
__device__ float  g_psum  [(size_t)BH * S * 32];  // [z,q,32] row partial sums
__device__ float  g_rowinv[(size_t)BH * S];       // [z,q] 1/rowsum

// ---------------------------------------------------------------------------
// Helpers
// ---------------------------------------------------------------------------
__device__ __forceinline__ uint32_t smem_u32(const void* p) {
    uint32_t a;
    asm("{ .reg .u64 t; cvta.to.shared.u64 t, %1; cvt.u32.u64 %0, t; }" : "=r"(a) : "l"(p));
    return a;
}
// pack two fp32 -> bf16x2, e0 in low half
__device__ __forceinline__ uint32_t cvt2(float e0, float e1) {
    uint32_t r;
    asm("cvt.rn.bf16x2.f32 %0, %1, %2;" : "=r"(r) : "f"(e1), "f"(e0));
    return r;
}
__device__ __forceinline__ void pack_hilo_bf(float4 v, uint2& hi, uint2& lo) {
    uint32_t h01 = cvt2(v.x, v.y);
    uint32_t h23 = cvt2(v.z, v.w);
    float hf0 = __uint_as_float(h01 << 16), hf1 = __uint_as_float(h01 & 0xFFFF0000u);
    float hf2 = __uint_as_float(h23 << 16), hf3 = __uint_as_float(h23 & 0xFFFF0000u);
    lo = make_uint2(cvt2(v.x - hf0, v.y - hf1), cvt2(v.z - hf2, v.w - hf3));
    hi = make_uint2(h01, h23);
}
__device__ __forceinline__ void pack_hilo_h(float4 v, uint2& hi, uint2& lo) {
    __half2 h01 = __floats2half2_rn(v.x, v.y);
    __half2 h23 = __floats2half2_rn(v.z, v.w);
    float2 f01 = __half22float2(h01), f23 = __half22float2(h23);
    __half2 l01 = __floats2half2_rn(v.x - f01.x, v.y - f01.y);
    __half2 l23 = __floats2half2_rn(v.z - f23.x, v.w - f23.y);
    hi = make_uint2(*(uint32_t*)&h01, *(uint32_t*)&h23);
    lo = make_uint2(*(uint32_t*)&l01, *(uint32_t*)&l23);
}
#define LDSM_X4(r0, r1, r2, r3, addr) \
    asm volatile("ldmatrix.sync.aligned.m8n8.x4.shared.b16 {%0,%1,%2,%3}, [%4];" \
        : "=r"(r0), "=r"(r1), "=r"(r2), "=r"(r3) : "r"(addr))

__device__ __forceinline__ void mma_bf16(float* d, const uint32_t* a, const uint32_t* b) {
    asm volatile(
        "mma.sync.aligned.m16n8k16.row.col.f32.bf16.bf16.f32 "
        "{%0,%1,%2,%3}, {%4,%5,%6,%7}, {%8,%9}, {%0,%1,%2,%3};"
        : "+f"(d[0]), "+f"(d[1]), "+f"(d[2]), "+f"(d[3])
        : "r"(a[0]), "r"(a[1]), "r"(a[2]), "r"(a[3]), "r"(b[0]), "r"(b[1]));
}
__device__ __forceinline__ void mma_f16(float* d, const uint32_t* a, const uint32_t* b) {
    asm volatile(
        "mma.sync.aligned.m16n8k16.row.col.f32.f16.f16.f32 "
        "{%0,%1,%2,%3}, {%4,%5,%6,%7}, {%8,%9}, {%0,%1,%2,%3};"
        : "+f"(d[0]), "+f"(d[1]), "+f"(d[2]), "+f"(d[3])
        : "r"(a[0]), "r"(a[1]), "r"(a[2]), "r"(a[3]), "r"(b[0]), "r"(b[1]));
}

// ---------------------------------------------------------------------------
// Generic split-precision mma.sync GEMM.  C = A[M,K] @ Bmat[N,K]^T (k-major).
// CTA tile: 128 x NTILE.  8 warps as (4 m) x (2 n).
// MODE 0/1/2: Q/K/V projection (bf16x3).  MODE 3: O projection (bf16x3).
// MODE 4: scores + exp(fp16 out) + partial rowsums (bf16x3, smem-staged store).
// MODE 5: ctx = normalized attn @ V (A exact fp16, V fp16 hi/lo -> 2 MMAs).
// ---------------------------------------------------------------------------
static constexpr int A_SZ = 128 * 80;       // one A buffer (hi or lo), 80B rows
static constexpr int SM_TOTAL = 4 * A_SZ + 4 * (128 * 80);  // 81920

template <int MODE>
__global__ __launch_bounds__(256, 1)
void mm_gemm(const float* __restrict__ Ain, const float* __restrict__ Bin,
             const float* __restrict__ bias, float* __restrict__ Cout)
{
    constexpr int NTILE = (MODE == 5) ? 64 : 128;
    constexpr int NC    = (MODE == 4) ? 2 : (MODE == 5) ? 64 : 32;  // k chunks of 32
    constexpr int LDA   = (MODE == 4) ? 64 : (MODE == 5) ? 2048 : 1024;
    constexpr int LDB   = (MODE == 4) ? 64 : (MODE == 5) ? 2048 : 1024;
    constexpr int WN    = NTILE / 2;
    constexpr int NF    = WN / 8;
    constexpr int B_SZ  = NTILE * 80;
    constexpr int OFFB0 = 4 * A_SZ;

    extern __shared__ char smem[];
    const uint32_t sb = smem_u32(smem);
    const int tid = threadIdx.x, wid = tid >> 5, l = tid & 31;
    const int wm = wid >> 1, wn = wid & 1;
    const int bn = blockIdx.x, bm = blockIdx.y;
    const int z  = (MODE >= 4) ? blockIdx.z : 0;

    const float* Abase = nullptr;
    const float* Bbase;
    if constexpr (MODE == 4)      { Abase = g_Q + (size_t)z * S * D; Bbase = g_K  + (size_t)z * S * D; }
    else if constexpr (MODE == 5) { Bbase = g_Vt + (size_t)z * D * S; }
    else if constexpr (MODE == 3) { Abase = g_ctx;                    Bbase = Bin; }
    else                          { Abase = Ain;                      Bbase = Bin; }

    // global load mapping
    const int arow = tid >> 1, acol = (tid & 1) * 16;
    const int browL = (NTILE == 128) ? (tid >> 1) : (tid >> 2);
    const int bcolL = (NTILE == 128) ? (tid & 1) * 16 : (tid & 3) * 8;
    constexpr int NBL = (NTILE == 128) ? 4 : 2;

    const float* aG = (MODE == 5) ? nullptr : (Abase + (size_t)(bm * 128 + arow) * LDA + acol);
    const float* bG = Bbase + (size_t)(bn * NTILE + browL) * LDB + bcolL;
    const __half* aGh = nullptr;
    if constexpr (MODE == 5)
        aGh = g_expS + (size_t)z * S * S + (size_t)(bm * 128 + arow) * S + (tid & 1) * 16;

    // ldmatrix per-lane selectors
    const int aRowSel = ((l >> 3) & 1) * 8 + (l & 7);
    const int aKsel   = ((l >> 4) & 1) * 16;
    const int bRowSel = ((l >> 4) & 1) * 8 + (l & 7);
    const int bKsel   = ((l >> 3) & 1) * 16;

    float dacc[2][NF][4];
    #pragma unroll
    for (int mf = 0; mf < 2; mf++)
        #pragma unroll
        for (int nf = 0; nf < NF; nf++)
            #pragma unroll
            for (int u = 0; u < 4; u++) dacc[mf][nf][u] = 0.f;

    float4 aR[4], bR[NBL];
    uint4  aRh[2];
    if constexpr (MODE == 5) {
        #pragma unroll
        for (int i = 0; i < 2; i++) aRh[i] = *(const uint4*)(aGh + 8 * i);
    } else {
        #pragma unroll
        for (int i = 0; i < 4; i++) aR[i] = *(const float4*)(aG + 4 * i);
    }
    #pragma unroll
    for (int i = 0; i < NBL; i++) bR[i] = *(const float4*)(bG + 4 * i);

    // stage chunk 0
    {
        if constexpr (MODE == 5) {
            #pragma unroll
            for (int i = 0; i < 2; i++)
                *(uint4*)(smem + arow * 80 + (tid & 1) * 32 + 16 * i) = aRh[i];
        } else {
            #pragma unroll
            for (int i = 0; i < 4; i++) {
                uint2 hi, lo; pack_hilo_bf(aR[i], hi, lo);
                const int off = arow * 80 + (acol + 4 * i) * 2;
                *(uint2*)(smem + off)        = hi;
                *(uint2*)(smem + A_SZ + off) = lo;
            }
        }
        #pragma unroll
        for (int i = 0; i < NBL; i++) {
            uint2 hi, lo;
            if constexpr (MODE == 5) pack_hilo_h(bR[i], hi, lo);
            else                     pack_hilo_bf(bR[i], hi, lo);
            const int off = browL * 80 + (bcolL + 4 * i) * 2;
            *(uint2*)(smem + OFFB0 + off)        = hi;
            *(uint2*)(smem + OFFB0 + B_SZ + off) = lo;
        }
    }
    __syncthreads();

    for (int c = 0; c < NC; c++) {
        const int buf = c & 1;
        if (c + 1 < NC) {
            if constexpr (MODE == 5) {
                #pragma unroll
                for (int i = 0; i < 2; i++) aRh[i] = *(const uint4*)(aGh + (c + 1) * 32 + 8 * i);
            } else {
                #pragma unroll
                for (int i = 0; i < 4; i++) aR[i] = *(const float4*)(aG + (c + 1) * 32 + 4 * i);
            }
            #pragma unroll
            for (int i = 0; i < NBL; i++) bR[i] = *(const float4*)(bG + (c + 1) * 32 + 4 * i);
        }

        const uint32_t aB = sb + buf * 2 * A_SZ;
        const uint32_t bB = sb + OFFB0 + buf * 2 * B_SZ;

        #pragma unroll
        for (int s = 0; s < 2; s++) {
            if constexpr (MODE == 5) {
                uint32_t af[2][4];
                #pragma unroll
                for (int mf = 0; mf < 2; mf++) {
                    const uint32_t ad = aB + (wm * 32 + mf * 16 + aRowSel) * 80 + s * 32 + aKsel;
                    LDSM_X4(af[mf][0], af[mf][1], af[mf][2], af[mf][3], ad);
                }
                uint32_t bf[NF][2][2];
                #pragma unroll
                for (int np = 0; np < NF / 2; np++)
                    #pragma unroll
                    for (int hl = 0; hl < 2; hl++) {
                        uint32_t r0, r1, r2, r3;
                        const uint32_t bd = bB + hl * B_SZ +
                            (wn * WN + np * 16 + bRowSel) * 80 + s * 32 + bKsel;
                        LDSM_X4(r0, r1, r2, r3, bd);
                        bf[2 * np][hl][0] = r0; bf[2 * np][hl][1] = r1;
                        bf[2 * np + 1][hl][0] = r2; bf[2 * np + 1][hl][1] = r3;
                    }
                #pragma unroll
                for (int mf = 0; mf < 2; mf++)
                    #pragma unroll
                    for (int nf = 0; nf < NF; nf++) {
                        mma_f16(dacc[mf][nf], af[mf], bf[nf][0]);   // A * V_hi
                        mma_f16(dacc[mf][nf], af[mf], bf[nf][1]);   // A * V_lo
                    }
            } else {
                uint32_t af[2][2][4];
                #pragma unroll
                for (int mf = 0; mf < 2; mf++)
                    #pragma unroll
                    for (int hl = 0; hl < 2; hl++) {
                        const uint32_t ad = aB + hl * A_SZ +
                            (wm * 32 + mf * 16 + aRowSel) * 80 + s * 32 + aKsel;
                        LDSM_X4(af[mf][hl][0], af[mf][hl][1], af[mf][hl][2], af[mf][hl][3], ad);
                    }
                uint32_t bf[NF][2][2];
                #pragma unroll
                for (int np = 0; np < NF / 2; np++)
                    #pragma unroll
                    for (int hl = 0; hl < 2; hl++) {
                        uint32_t r0, r1, r2, r3;
                        const uint32_t bd = bB + hl * B_SZ +
                            (wn * WN + np * 16 + bRowSel) * 80 + s * 32 + bKsel;
                        LDSM_X4(r0, r1, r2, r3, bd);
                        bf[2 * np][hl][0] = r0; bf[2 * np][hl][1] = r1;
                        bf[2 * np + 1][hl][0] = r2; bf[2 * np + 1][hl][1] = r3;
                    }
                #pragma unroll
                for (int mf = 0; mf < 2; mf++)
                    #pragma unroll
                    for (int nf = 0; nf < NF; nf++) {
                        mma_bf16(dacc[mf][nf], af[mf][0], bf[nf][0]);   // hi*hi
                        mma_bf16(dacc[mf][nf], af[mf][1], bf[nf][0]);   // lo*hi
                        mma_bf16(dacc[mf][nf], af[mf][0], bf[nf][1]);   // hi*lo
                    }
            }
        }

        if (c + 1 < NC) {
            __syncthreads();
            const int nb = (c + 1) & 1;
            if constexpr (MODE == 5) {
                #pragma unroll
                for (int i = 0; i < 2; i++)
                    *(uint4*)(smem + nb * 2 * A_SZ + arow * 80 + (tid & 1) * 32 + 16 * i) = aRh[i];
            } else {
                #pragma unroll
                for (int i = 0; i < 4; i++) {
                    uint2 hi, lo; pack_hilo_bf(aR[i], hi, lo);
                    const int off = nb * 2 * A_SZ + arow * 80 + (acol + 4 * i) * 2;
                    *(uint2*)(smem + off)        = hi;
                    *(uint2*)(smem + A_SZ + off) = lo;
                }
            }
            #pragma unroll
            for (int i = 0; i < NBL; i++) {
                uint2 hi, lo;
                if constexpr (MODE == 5) pack_hilo_h(bR[i], hi, lo);
                else                     pack_hilo_bf(bR[i], hi, lo);
                const int off = OFFB0 + nb * 2 * B_SZ + browL * 80 + (bcolL + 4 * i) * 2;
                *(uint2*)(smem + off)        = hi;
                *(uint2*)(smem + B_SZ + off) = lo;
            }
            __syncthreads();
        }
    }

    // ------------------------- epilogue -------------------------
    const int g  = l >> 2;                // row group within fragment
    const int cq = (l & 3) * 2;           // col pair within fragment

    if constexpr (MODE == 4) __syncthreads();   // operands smem -> staging reuse

    #pragma unroll
    for (int mf = 0; mf < 2; mf++) {
        const int row0 = bm * 128 + wm * 32 + mf * 16 + g;
        const int row1 = row0 + 8;
        float rs0 = 0.f, rs1 = 0.f;
        float inv0 = 1.f, inv1 = 1.f;
        if constexpr (MODE == 5) {
            inv0 = g_rowinv[(size_t)z * S + row0];
            inv1 = g_rowinv[(size_t)z * S + row1];
        }
        #pragma unroll
        for (int nf = 0; nf < NF; nf++) {
            const int gcol = bn * NTILE + wn * WN + nf * 8 + cq;
            float v0 = dacc[mf][nf][0], v1 = dacc[mf][nf][1];
            float v2 = dacc[mf][nf][2], v3 = dacc[mf][nf][3];

            if constexpr (MODE <= 2) {
                const float b0 = __ldg(bias + gcol), b1 = __ldg(bias + gcol + 1);
                v0 += b0; v1 += b1; v2 += b0; v3 += b1;
                if (MODE == 0) { v0 *= 0.125f; v1 *= 0.125f; v2 *= 0.125f; v3 *= 0.125f; }
                const int hh = gcol >> 6, dd = gcol & 63;
                const int bb0 = row0 >> 11, ss0 = row0 & (S - 1);
                const int bb1 = row1 >> 11, ss1 = row1 & (S - 1);
                if constexpr (MODE == 0) {
                    *(float2*)(g_Q + (((size_t)(bb0 * H + hh)) * S + ss0) * D + dd) = make_float2(v0, v1);
                    *(float2*)(g_Q + (((size_t)(bb1 * H + hh)) * S + ss1) * D + dd) = make_float2(v2, v3);
                } else if constexpr (MODE == 1) {
                    *(float2*)(g_K + (((size_t)(bb0 * H + hh)) * S + ss0) * D + dd) = make_float2(v0, v1);
                    *(float2*)(g_K + (((size_t)(bb1 * H + hh)) * S + ss1) * D + dd) = make_float2(v2, v3);
                } else {
                    float* vt0 = g_Vt + (((size_t)(bb0 * H + hh)) * D + dd) * S + ss0;
                    float* vt1 = g_Vt + (((size_t)(bb1 * H + hh)) * D + dd) * S + ss1;
                    vt0[0] = v0; vt0[S] = v1;
                    vt1[0] = v2; vt1[S] = v3;
                }
            } else if constexpr (MODE == 3) {
                const float b0 = __ldg(bias + gcol), b1 = __ldg(bias + gcol + 1);
                *(float2*)(Cout + (size_t)row0 * E + gcol) = make_float2(v0 + b0, v1 + b1);
                *(float2*)(Cout + (size_t)row1 * E + gcol) = make_float2(v2 + b0, v3 + b1);
            } else if constexpr (MODE == 4) {
                const float e0 = __expf(v0), e1 = __expf(v1);
                const float e2 = __expf(v2), e3 = __expf(v3);
                rs0 += e0 + e1; rs1 += e2 + e3;
                __half2 p01 = __floats2half2_rn(e0, e1);
                __half2 p23 = __floats2half2_rn(e2, e3);
                const int srow = wm * 32 + mf * 16 + g;
                const int scol = wn * 64 + nf * 8 + cq;
                *(__half2*)(smem + srow * 272 + scol * 2)       = p01;
                *(__half2*)(smem + (srow + 8) * 272 + scol * 2) = p23;
            } else {  // MODE 5
                const int bb = z >> 4, hh = z & (H - 1);
                const int dd = wn * WN + nf * 8 + cq;
                *(float2*)(g_ctx + ((size_t)(bb * S + row0)) * E + hh * D + dd) =
                    make_float2(v0 * inv0, v1 * inv0);
                *(float2*)(g_ctx + ((size_t)(bb * S + row1)) * E + hh * D + dd) =
                    make_float2(v2 * inv1, v3 * inv1);
            }
        }
        if constexpr (MODE == 4) {
            rs0 += __shfl_xor_sync(0xffffffffu, rs0, 1);
            rs0 += __shfl_xor_sync(0xffffffffu, rs0, 2);
            rs1 += __shfl_xor_sync(0xffffffffu, rs1, 1);
            rs1 += __shfl_xor_sync(0xffffffffu, rs1, 2);
            if ((l & 3) == 0) {
                const int slot = bn * 2 + wn;
                g_psum[((size_t)z * S + row0) * 32 + slot] = rs0;
                g_psum[((size_t)z * S + row1) * 32 + slot] = rs1;
            }
        }
    }

    if constexpr (MODE == 4) {
        // coalesced fp16 copy-out of the 128x128 tile
        __syncthreads();
        const int r   = tid >> 1;
        const int seg = (tid & 1) * 8;
        uint4* gp = (uint4*)((char*)g_expS +
            ((size_t)z * S + bm * 128 + r) * (S * 2) + bn * 256);
        #pragma unroll
        for (int i = 0; i < 8; i++)
            gp[seg + i] = *(const uint4*)(smem + r * 272 + (seg + i) * 16);
    }
}

// ---------------------------------------------------------------------------
// mean over heads + rowinv: out2[b,q,k] = sum_h expS[b,h,q,k]/(rowsum_h * H)
// ---------------------------------------------------------------------------
__global__ __launch_bounds__(256)
void mean_kernel(float* __restrict__ out2)
{
    const int r = blockIdx.x;                  // 0..BS-1
    const int b = r >> 11, q = r & (S - 1);
    const int tid = threadIdx.x;

    __shared__ float inv[H];
    if (tid < H) {
        const float4* ps = (const float4*)(g_psum + ((size_t)(b * H + tid) * S + q) * 32);
        float s = 0.f;
        #pragma unroll
        for (int i = 0; i < 8; i++) {
            float4 t = ps[i];
            s += (t.x + t.y) + (t.z + t.w);
        }
        const float ri = 1.0f / s;
        g_rowinv[(size_t)(b * H + tid) * S + q] = ri;
        inv[tid] = ri * (1.0f / (float)H);
    }
    __syncthreads();

    float acc[8] = {0.f, 0.f, 0.f, 0.f, 0.f, 0.f, 0.f, 0.f};
    #pragma unroll
    for (int h = 0; h < H; h++) {
        const uint4 t = *(const uint4*)((const char*)g_expS +
            ((size_t)(b * H + h) * S + q) * (S * 2) + tid * 16);
        const float iv = inv[h];
        const __half2* hp = (const __half2*)&t;
        #pragma unroll
        for (int j = 0; j < 4; j++) {
            float2 f = __half22float2(hp[j]);
            acc[2 * j]     += f.x * iv;
            acc[2 * j + 1] += f.y * iv;
        }
    }
    float* o = out2 + (size_t)r * S + tid * 8;
    *(float4*)o       = make_float4(acc[0], acc[1], acc[2], acc[3]);
    *(float4*)(o + 4) = make_float4(acc[4], acc[5], acc[6], acc[7]);
}

// ---------------------------------------------------------------------------
// Launch
// ---------------------------------------------------------------------------
extern "C" void kernel_launch(void* const* d_in, const int* in_sizes, int n_in,
                              void* d_out, int out_size)
{
    const float* query = (const float*)d_in[0];
    const float* key   = (const float*)d_in[1];
    const float* value = (const float*)d_in[2];
    const float* Wq = (const float*)d_in[3];
    const float* bq = (const float*)d_in[4];
    const float* Wk = (const float*)d_in[5];
    const float* bk = (const float*)d_in[6];
    const float* Wv = (const float*)d_in[7];
    const float* bv = (const float*)d_in[8];
    const float* Wo = (const float*)d_in[9];
    const float* bo = (const float*)d_in[10];

    float* out       = (float*)d_out;
    float* attn_mean = out + (size_t)BS * E;

    cudaFuncSetAttribute(mm_gemm<0>, cudaFuncAttributeMaxDynamicSharedMemorySize, SM_TOTAL);
    cudaFuncSetAttribute(mm_gemm<1>, cudaFuncAttributeMaxDynamicSharedMemorySize, SM_TOTAL);
    cudaFuncSetAttribute(mm_gemm<2>, cudaFuncAttributeMaxDynamicSharedMemorySize, SM_TOTAL);
    cudaFuncSetAttribute(mm_gemm<3>, cudaFuncAttributeMaxDynamicSharedMemorySize, SM_TOTAL);
    cudaFuncSetAttribute(mm_gemm<4>, cudaFuncAttributeMaxDynamicSharedMemorySize, SM_TOTAL);
    cudaFuncSetAttribute(mm_gemm<5>, cudaFuncAttributeMaxDynamicSharedMemorySize, SM_TOTAL);

    const dim3 projGrid(E / 128, BS / 128);                 // (8, 64)
    mm_gemm<0><<<projGrid, 256, SM_TOTAL>>>(query, Wq, bq, nullptr);
    mm_gemm<1><<<projGrid, 256, SM_TOTAL>>>(key,   Wk, bk, nullptr);
    mm_gemm<2><<<projGrid, 256, SM_TOTAL>>>(value, Wv, bv, nullptr);

    mm_gemm<4><<<dim3(S / 128, S / 128, BH), 256, SM_TOTAL>>>(nullptr, nullptr, nullptr, nullptr);

    mean_kernel<<<BS, 256>>>(attn_mean);

    mm_gemm<5><<<dim3(1, S / 128, BH), 256, SM_TOTAL>>>(nullptr, nullptr, nullptr, nullptr);

    mm_gemm<3><<<projGrid, 256, SM_TOTAL>>>(nullptr, Wo, bo, out);
}

// round 13
// speedup vs baseline: 3.0652x; 1.0391x over previous
#include <cuda_runtime.h>
#include <cuda_bf16.h>
#include <cuda_fp16.h>
#include <cstdint>
#include <cstddef>

// Problem constants
static constexpr int B  = 4;
static constexpr int S  = 2048;
static constexpr int E  = 1024;
static constexpr int H  = 16;
static constexpr int D  = 64;
static constexpr int BS = B * S;    // 8192
static constexpr int BH = B * H;    // 64

// ---------------------------------------------------------------------------
// Scratch
// ---------------------------------------------------------------------------
__device__ uint32_t g_Qh  [(size_t)BH * S * 32];  // [z,s,d/2] bf16x2 hi (Q/8)
__device__ uint32_t g_Ql  [(size_t)BH * S * 32];  // [z,s,d/2] bf16x2 lo
__device__ uint32_t g_Kh  [(size_t)BH * S * 32];
__device__ uint32_t g_Kl  [(size_t)BH * S * 32];
__device__ float    g_Vt  [(size_t)BH * D * S];   // [z,d,s]
__device__ float    g_ctx [(size_t)BS * E];       // [b,s,e]
__device__ __half   g_expS[(size_t)BH * S * S];   // [z,q,k] unnormalized exp
__device__ float    g_psum[(size_t)BH * S * 32];  // [z,q,32] row partial sums
__device__ float    g_rowinv[(size_t)BH * S];     // [z,q] 1/rowsum

// ---------------------------------------------------------------------------
// Helpers
// ---------------------------------------------------------------------------
__device__ __forceinline__ uint32_t smem_u32(const void* p) {
    uint32_t a;
    asm("{ .reg .u64 t; cvta.to.shared.u64 t, %1; cvt.u32.u64 %0, t; }" : "=r"(a) : "l"(p));
    return a;
}
// pack two fp32 -> bf16x2, e0 in low half
__device__ __forceinline__ uint32_t cvt2(float e0, float e1) {
    uint32_t r;
    asm("cvt.rn.bf16x2.f32 %0, %1, %2;" : "=r"(r) : "f"(e1), "f"(e0));
    return r;
}
__device__ __forceinline__ void pack2(float v0, float v1, uint32_t& hi, uint32_t& lo) {
    hi = cvt2(v0, v1);
    float f0 = __uint_as_float(hi << 16), f1 = __uint_as_float(hi & 0xFFFF0000u);
    lo = cvt2(v0 - f0, v1 - f1);
}
__device__ __forceinline__ void pack_hilo_bf(float4 v, uint2& hi, uint2& lo) {
    pack2(v.x, v.y, hi.x, lo.x);
    pack2(v.z, v.w, hi.y, lo.y);
}
__device__ __forceinline__ void pack_hilo_h(float4 v, uint2& hi, uint2& lo) {
    __half2 h01 = __floats2half2_rn(v.x, v.y);
    __half2 h23 = __floats2half2_rn(v.z, v.w);
    float2 f01 = __half22float2(h01), f23 = __half22float2(h23);
    __half2 l01 = __floats2half2_rn(v.x - f01.x, v.y - f01.y);
    __half2 l23 = __floats2half2_rn(v.z - f23.x, v.w - f23.y);
    hi = make_uint2(*(uint32_t*)&h01, *(uint32_t*)&h23);
    lo = make_uint2(*(uint32_t*)&l01, *(uint32_t*)&l23);
}
#define LDSM_X4(r0, r1, r2, r3, addr) \
    asm volatile("ldmatrix.sync.aligned.m8n8.x4.shared.b16 {%0,%1,%2,%3}, [%4];" \
        : "=r"(r0), "=r"(r1), "=r"(r2), "=r"(r3) : "r"(addr))

__device__ __forceinline__ void mma_bf16(float* d, const uint32_t* a, const uint32_t* b) {
    asm volatile(
        "mma.sync.aligned.m16n8k16.row.col.f32.bf16.bf16.f32 "
        "{%0,%1,%2,%3}, {%4,%5,%6,%7}, {%8,%9}, {%0,%1,%2,%3};"
        : "+f"(d[0]), "+f"(d[1]), "+f"(d[2]), "+f"(d[3])
        : "r"(a[0]), "r"(a[1]), "r"(a[2]), "r"(a[3]), "r"(b[0]), "r"(b[1]));
}
__device__ __forceinline__ void mma_f16(float* d, const uint32_t* a, const uint32_t* b) {
    asm volatile(
        "mma.sync.aligned.m16n8k16.row.col.f32.f16.f16.f32 "
        "{%0,%1,%2,%3}, {%4,%5,%6,%7}, {%8,%9}, {%0,%1,%2,%3};"
        : "+f"(d[0]), "+f"(d[1]), "+f"(d[2]), "+f"(d[3])
        : "r"(a[0]), "r"(a[1]), "r"(a[2]), "r"(a[3]), "r"(b[0]), "r"(b[1]));
}

// ---------------------------------------------------------------------------
// Scores kernel: expS[z,q,k] = exp(Qs . K)  (Q pre-scaled by 1/8)
// 128x128 CTA tile, 8 warps (4m x 2n).  Operands pre-split bf16 hi/lo.
// K=64 staged fully up-front; epilogue through swizzled smem staging.
// smem: 8 chunk buffers of 128*80 (QH0 QH1 QL0 QL1 KH0 KH1 KL0 KL1) = 81920,
//       then fp16 staging tile 128*256 = 32768.  Total 114688.
// ---------------------------------------------------------------------------
static constexpr int SC_STAGE = 81920;
static constexpr int SC_SMEM  = 81920 + 32768;

__global__ __launch_bounds__(256, 1)
void scores_k()
{
    extern __shared__ char smem[];
    const uint32_t sb = smem_u32(smem);
    const int tid = threadIdx.x, wid = tid >> 5, l = tid & 31;
    const int wm = wid >> 1, wn = wid & 1;
    const int bn = blockIdx.x, bm = blockIdx.y, z = blockIdx.z;

    // ---- stage operands: raw 16B copies, no conversion ----
    {
        const int row = tid >> 1, c = tid & 1;   // chunk c = k block [c*32, c*32+32)
        const uint4* qh = (const uint4*)(g_Qh + ((size_t)z * S + bm * 128 + row) * 32) + c * 4;
        const uint4* ql = (const uint4*)(g_Ql + ((size_t)z * S + bm * 128 + row) * 32) + c * 4;
        const uint4* kh = (const uint4*)(g_Kh + ((size_t)z * S + bn * 128 + row) * 32) + c * 4;
        const uint4* kl = (const uint4*)(g_Kl + ((size_t)z * S + bn * 128 + row) * 32) + c * 4;
        char* dq = smem + c * 10240 + row * 80;
        #pragma unroll
        for (int j = 0; j < 4; j++) *(uint4*)(dq + j * 16)         = qh[j];
        #pragma unroll
        for (int j = 0; j < 4; j++) *(uint4*)(dq + 20480 + j * 16) = ql[j];
        #pragma unroll
        for (int j = 0; j < 4; j++) *(uint4*)(dq + 40960 + j * 16) = kh[j];
        #pragma unroll
        for (int j = 0; j < 4; j++) *(uint4*)(dq + 61440 + j * 16) = kl[j];
    }
    __syncthreads();

    const int aRowSel = ((l >> 3) & 1) * 8 + (l & 7);
    const int aKsel   = ((l >> 4) & 1) * 16;
    const int bRowSel = ((l >> 4) & 1) * 8 + (l & 7);
    const int bKsel   = ((l >> 3) & 1) * 16;

    float dacc[2][8][4];
    #pragma unroll
    for (int mf = 0; mf < 2; mf++)
        #pragma unroll
        for (int nf = 0; nf < 8; nf++)
            #pragma unroll
            for (int u = 0; u < 4; u++) dacc[mf][nf][u] = 0.f;

    #pragma unroll
    for (int c = 0; c < 2; c++) {
        #pragma unroll
        for (int s = 0; s < 2; s++) {
            uint32_t af[2][2][4];
            #pragma unroll
            for (int mf = 0; mf < 2; mf++)
                #pragma unroll
                for (int hl = 0; hl < 2; hl++) {
                    const uint32_t ad = sb + hl * 20480 + c * 10240 +
                        (wm * 32 + mf * 16 + aRowSel) * 80 + s * 32 + aKsel;
                    LDSM_X4(af[mf][hl][0], af[mf][hl][1], af[mf][hl][2], af[mf][hl][3], ad);
                }
            uint32_t bf[8][2][2];
            #pragma unroll
            for (int np = 0; np < 4; np++)
                #pragma unroll
                for (int hl = 0; hl < 2; hl++) {
                    uint32_t r0, r1, r2, r3;
                    const uint32_t bd = sb + 40960 + hl * 20480 + c * 10240 +
                        (wn * 64 + np * 16 + bRowSel) * 80 + s * 32 + bKsel;
                    LDSM_X4(r0, r1, r2, r3, bd);
                    bf[2 * np][hl][0] = r0; bf[2 * np][hl][1] = r1;
                    bf[2 * np + 1][hl][0] = r2; bf[2 * np + 1][hl][1] = r3;
                }
            #pragma unroll
            for (int mf = 0; mf < 2; mf++)
                #pragma unroll
                for (int nf = 0; nf < 8; nf++) {
                    mma_bf16(dacc[mf][nf], af[mf][0], bf[nf][0]);   // hi*hi
                    mma_bf16(dacc[mf][nf], af[mf][1], bf[nf][0]);   // lo*hi
                    mma_bf16(dacc[mf][nf], af[mf][0], bf[nf][1]);   // hi*lo
                }
        }
    }

    // ---- epilogue: exp -> swizzled staging, partial rowsums ----
    const int g  = l >> 2;
    const int cq = (l & 3) * 2;

    #pragma unroll
    for (int mf = 0; mf < 2; mf++) {
        const int row0 = bm * 128 + wm * 32 + mf * 16 + g;
        const int row1 = row0 + 8;
        float rs0 = 0.f, rs1 = 0.f;
        #pragma unroll
        for (int nf = 0; nf < 8; nf++) {
            const float e0 = __expf(dacc[mf][nf][0]), e1 = __expf(dacc[mf][nf][1]);
            const float e2 = __expf(dacc[mf][nf][2]), e3 = __expf(dacc[mf][nf][3]);
            rs0 += e0 + e1; rs1 += e2 + e3;
            __half2 p01 = __floats2half2_rn(e0, e1);
            __half2 p23 = __floats2half2_rn(e2, e3);
            const int srow0 = wm * 32 + mf * 16 + g;
            const int srow1 = srow0 + 8;
            const int chunk = wn * 8 + nf;          // 16B chunk index (col*2/16)
            *(__half2*)(smem + SC_STAGE + srow0 * 256 +
                        ((chunk ^ (srow0 & 15)) * 16) + (l & 3) * 4) = p01;
            *(__half2*)(smem + SC_STAGE + srow1 * 256 +
                        ((chunk ^ (srow1 & 15)) * 16) + (l & 3) * 4) = p23;
        }
        rs0 += __shfl_xor_sync(0xffffffffu, rs0, 1);
        rs0 += __shfl_xor_sync(0xffffffffu, rs0, 2);
        rs1 += __shfl_xor_sync(0xffffffffu, rs1, 1);
        rs1 += __shfl_xor_sync(0xffffffffu, rs1, 2);
        if ((l & 3) == 0) {
            const int slot = bn * 2 + wn;
            g_psum[((size_t)z * S + row0) * 32 + slot] = rs0;
            g_psum[((size_t)z * S + row1) * 32 + slot] = rs1;
        }
    }
    __syncthreads();

    // ---- coalesced copy-out (conflict-free via swizzle) ----
    {
        const int j = tid & 15, rowbase = tid >> 4;
        #pragma unroll
        for (int i = 0; i < 8; i++) {
            const int row = rowbase + 16 * i;
            const uint4 v = *(const uint4*)(smem + SC_STAGE + row * 256 +
                                            ((j ^ (row & 15)) * 16));
            *(uint4*)((char*)g_expS + ((size_t)z * S + bm * 128 + row) * (S * 2) +
                      bn * 256 + j * 16) = v;
        }
    }
}

// ---------------------------------------------------------------------------
// Generic split-precision mma.sync GEMM.  C = A[M,K] @ Bmat[N,K]^T (k-major).
// MODE 0/1/2: Q/K/V projection (bf16x3).  MODE 3: O projection (bf16x3).
// MODE 5: ctx = normalized attn @ V (A exact fp16, V fp16 hi/lo -> 2 MMAs).
// ---------------------------------------------------------------------------
static constexpr int A_SZ = 128 * 80;
static constexpr int SM_TOTAL = 4 * A_SZ + 4 * (128 * 80);  // 81920

template <int MODE>
__global__ __launch_bounds__(256, 1)
void mm_gemm(const float* __restrict__ Ain, const float* __restrict__ Bin,
             const float* __restrict__ bias, float* __restrict__ Cout)
{
    constexpr int NTILE = (MODE == 5) ? 64 : 128;
    constexpr int NC    = (MODE == 5) ? 64 : 32;
    constexpr int LDA   = (MODE == 5) ? 2048 : 1024;
    constexpr int LDB   = (MODE == 5) ? 2048 : 1024;
    constexpr int WN    = NTILE / 2;
    constexpr int NF    = WN / 8;
    constexpr int B_SZ  = NTILE * 80;
    constexpr int OFFB0 = 4 * A_SZ;

    extern __shared__ char smem[];
    const uint32_t sb = smem_u32(smem);
    const int tid = threadIdx.x, wid = tid >> 5, l = tid & 31;
    const int wm = wid >> 1, wn = wid & 1;
    const int bn = blockIdx.x, bm = blockIdx.y;
    const int z  = (MODE == 5) ? blockIdx.z : 0;

    const float* Abase = nullptr;
    const float* Bbase;
    if constexpr (MODE == 5)      { Bbase = g_Vt + (size_t)z * D * S; }
    else if constexpr (MODE == 3) { Abase = g_ctx; Bbase = Bin; }
    else                          { Abase = Ain;   Bbase = Bin; }

    const int arow = tid >> 1, acol = (tid & 1) * 16;
    const int browL = (NTILE == 128) ? (tid >> 1) : (tid >> 2);
    const int bcolL = (NTILE == 128) ? (tid & 1) * 16 : (tid & 3) * 8;
    constexpr int NBL = (NTILE == 128) ? 4 : 2;

    const float* aG = (MODE == 5) ? nullptr : (Abase + (size_t)(bm * 128 + arow) * LDA + acol);
    const float* bG = Bbase + (size_t)(bn * NTILE + browL) * LDB + bcolL;
    const __half* aGh = nullptr;
    if constexpr (MODE == 5)
        aGh = g_expS + (size_t)z * S * S + (size_t)(bm * 128 + arow) * S + (tid & 1) * 16;

    const int aRowSel = ((l >> 3) & 1) * 8 + (l & 7);
    const int aKsel   = ((l >> 4) & 1) * 16;
    const int bRowSel = ((l >> 4) & 1) * 8 + (l & 7);
    const int bKsel   = ((l >> 3) & 1) * 16;

    float dacc[2][NF][4];
    #pragma unroll
    for (int mf = 0; mf < 2; mf++)
        #pragma unroll
        for (int nf = 0; nf < NF; nf++)
            #pragma unroll
            for (int u = 0; u < 4; u++) dacc[mf][nf][u] = 0.f;

    float4 aR[4], bR[NBL];
    uint4  aRh[2];
    if constexpr (MODE == 5) {
        #pragma unroll
        for (int i = 0; i < 2; i++) aRh[i] = *(const uint4*)(aGh + 8 * i);
    } else {
        #pragma unroll
        for (int i = 0; i < 4; i++) aR[i] = *(const float4*)(aG + 4 * i);
    }
    #pragma unroll
    for (int i = 0; i < NBL; i++) bR[i] = *(const float4*)(bG + 4 * i);

    // stage chunk 0
    {
        if constexpr (MODE == 5) {
            #pragma unroll
            for (int i = 0; i < 2; i++)
                *(uint4*)(smem + arow * 80 + (tid & 1) * 32 + 16 * i) = aRh[i];
        } else {
            #pragma unroll
            for (int i = 0; i < 4; i++) {
                uint2 hi, lo; pack_hilo_bf(aR[i], hi, lo);
                const int off = arow * 80 + (acol + 4 * i) * 2;
                *(uint2*)(smem + off)        = hi;
                *(uint2*)(smem + A_SZ + off) = lo;
            }
        }
        #pragma unroll
        for (int i = 0; i < NBL; i++) {
            uint2 hi, lo;
            if constexpr (MODE == 5) pack_hilo_h(bR[i], hi, lo);
            else                     pack_hilo_bf(bR[i], hi, lo);
            const int off = browL * 80 + (bcolL + 4 * i) * 2;
            *(uint2*)(smem + OFFB0 + off)        = hi;
            *(uint2*)(smem + OFFB0 + B_SZ + off) = lo;
        }
    }
    __syncthreads();

    for (int c = 0; c < NC; c++) {
        const int buf = c & 1;
        if (c + 1 < NC) {
            if constexpr (MODE == 5) {
                #pragma unroll
                for (int i = 0; i < 2; i++) aRh[i] = *(const uint4*)(aGh + (c + 1) * 32 + 8 * i);
            } else {
                #pragma unroll
                for (int i = 0; i < 4; i++) aR[i] = *(const float4*)(aG + (c + 1) * 32 + 4 * i);
            }
            #pragma unroll
            for (int i = 0; i < NBL; i++) bR[i] = *(const float4*)(bG + (c + 1) * 32 + 4 * i);
        }

        const uint32_t aB = sb + buf * 2 * A_SZ;
        const uint32_t bB = sb + OFFB0 + buf * 2 * B_SZ;

        #pragma unroll
        for (int s = 0; s < 2; s++) {
            if constexpr (MODE == 5) {
                uint32_t af[2][4];
                #pragma unroll
                for (int mf = 0; mf < 2; mf++) {
                    const uint32_t ad = aB + (wm * 32 + mf * 16 + aRowSel) * 80 + s * 32 + aKsel;
                    LDSM_X4(af[mf][0], af[mf][1], af[mf][2], af[mf][3], ad);
                }
                uint32_t bf[NF][2][2];
                #pragma unroll
                for (int np = 0; np < NF / 2; np++)
                    #pragma unroll
                    for (int hl = 0; hl < 2; hl++) {
                        uint32_t r0, r1, r2, r3;
                        const uint32_t bd = bB + hl * B_SZ +
                            (wn * WN + np * 16 + bRowSel) * 80 + s * 32 + bKsel;
                        LDSM_X4(r0, r1, r2, r3, bd);
                        bf[2 * np][hl][0] = r0; bf[2 * np][hl][1] = r1;
                        bf[2 * np + 1][hl][0] = r2; bf[2 * np + 1][hl][1] = r3;
                    }
                #pragma unroll
                for (int mf = 0; mf < 2; mf++)
                    #pragma unroll
                    for (int nf = 0; nf < NF; nf++) {
                        mma_f16(dacc[mf][nf], af[mf], bf[nf][0]);
                        mma_f16(dacc[mf][nf], af[mf], bf[nf][1]);
                    }
            } else {
                uint32_t af[2][2][4];
                #pragma unroll
                for (int mf = 0; mf < 2; mf++)
                    #pragma unroll
                    for (int hl = 0; hl < 2; hl++) {
                        const uint32_t ad = aB + hl * A_SZ +
                            (wm * 32 + mf * 16 + aRowSel) * 80 + s * 32 + aKsel;
                        LDSM_X4(af[mf][hl][0], af[mf][hl][1], af[mf][hl][2], af[mf][hl][3], ad);
                    }
                uint32_t bf[NF][2][2];
                #pragma unroll
                for (int np = 0; np < NF / 2; np++)
                    #pragma unroll
                    for (int hl = 0; hl < 2; hl++) {
                        uint32_t r0, r1, r2, r3;
                        const uint32_t bd = bB + hl * B_SZ +
                            (wn * WN + np * 16 + bRowSel) * 80 + s * 32 + bKsel;
                        LDSM_X4(r0, r1, r2, r3, bd);
                        bf[2 * np][hl][0] = r0; bf[2 * np][hl][1] = r1;
                        bf[2 * np + 1][hl][0] = r2; bf[2 * np + 1][hl][1] = r3;
                    }
                #pragma unroll
                for (int mf = 0; mf < 2; mf++)
                    #pragma unroll
                    for (int nf = 0; nf < NF; nf++) {
                        mma_bf16(dacc[mf][nf], af[mf][0], bf[nf][0]);
                        mma_bf16(dacc[mf][nf], af[mf][1], bf[nf][0]);
                        mma_bf16(dacc[mf][nf], af[mf][0], bf[nf][1]);
                    }
            }
        }

        if (c + 1 < NC) {
            __syncthreads();
            const int nb = (c + 1) & 1;
            if constexpr (MODE == 5) {
                #pragma unroll
                for (int i = 0; i < 2; i++)
                    *(uint4*)(smem + nb * 2 * A_SZ + arow * 80 + (tid & 1) * 32 + 16 * i) = aRh[i];
            } else {
                #pragma unroll
                for (int i = 0; i < 4; i++) {
                    uint2 hi, lo; pack_hilo_bf(aR[i], hi, lo);
                    const int off = nb * 2 * A_SZ + arow * 80 + (acol + 4 * i) * 2;
                    *(uint2*)(smem + off)        = hi;
                    *(uint2*)(smem + A_SZ + off) = lo;
                }
            }
            #pragma unroll
            for (int i = 0; i < NBL; i++) {
                uint2 hi, lo;
                if constexpr (MODE == 5) pack_hilo_h(bR[i], hi, lo);
                else                     pack_hilo_bf(bR[i], hi, lo);
                const int off = OFFB0 + nb * 2 * B_SZ + browL * 80 + (bcolL + 4 * i) * 2;
                *(uint2*)(smem + off)        = hi;
                *(uint2*)(smem + B_SZ + off) = lo;
            }
            __syncthreads();
        }
    }

    // ------------------------- epilogue -------------------------
    const int g  = l >> 2;
    const int cq = (l & 3) * 2;

    #pragma unroll
    for (int mf = 0; mf < 2; mf++) {
        const int row0 = bm * 128 + wm * 32 + mf * 16 + g;
        const int row1 = row0 + 8;
        float inv0 = 1.f, inv1 = 1.f;
        if constexpr (MODE == 5) {
            inv0 = g_rowinv[(size_t)z * S + row0];
            inv1 = g_rowinv[(size_t)z * S + row1];
        }
        #pragma unroll
        for (int nf = 0; nf < NF; nf++) {
            const int gcol = bn * NTILE + wn * WN + nf * 8 + cq;
            float v0 = dacc[mf][nf][0], v1 = dacc[mf][nf][1];
            float v2 = dacc[mf][nf][2], v3 = dacc[mf][nf][3];

            if constexpr (MODE <= 2) {
                const float b0 = __ldg(bias + gcol), b1 = __ldg(bias + gcol + 1);
                v0 += b0; v1 += b1; v2 += b0; v3 += b1;
                if (MODE == 0) { v0 *= 0.125f; v1 *= 0.125f; v2 *= 0.125f; v3 *= 0.125f; }
                const int hh = gcol >> 6, dd = gcol & 63;
                const int bb0 = row0 >> 11, ss0 = row0 & (S - 1);
                const int bb1 = row1 >> 11, ss1 = row1 & (S - 1);
                if constexpr (MODE == 0 || MODE == 1) {
                    uint32_t hi0, lo0, hi1, lo1;
                    pack2(v0, v1, hi0, lo0);
                    pack2(v2, v3, hi1, lo1);
                    const size_t i0 = ((size_t)(bb0 * H + hh) * S + ss0) * 32 + (dd >> 1);
                    const size_t i1 = ((size_t)(bb1 * H + hh) * S + ss1) * 32 + (dd >> 1);
                    if constexpr (MODE == 0) {
                        g_Qh[i0] = hi0; g_Ql[i0] = lo0;
                        g_Qh[i1] = hi1; g_Ql[i1] = lo1;
                    } else {
                        g_Kh[i0] = hi0; g_Kl[i0] = lo0;
                        g_Kh[i1] = hi1; g_Kl[i1] = lo1;
                    }
                } else {
                    float* vt0 = g_Vt + (((size_t)(bb0 * H + hh)) * D + dd) * S + ss0;
                    float* vt1 = g_Vt + (((size_t)(bb1 * H + hh)) * D + dd) * S + ss1;
                    vt0[0] = v0; vt0[S] = v1;
                    vt1[0] = v2; vt1[S] = v3;
                }
            } else if constexpr (MODE == 3) {
                const float b0 = __ldg(bias + gcol), b1 = __ldg(bias + gcol + 1);
                *(float2*)(Cout + (size_t)row0 * E + gcol) = make_float2(v0 + b0, v1 + b1);
                *(float2*)(Cout + (size_t)row1 * E + gcol) = make_float2(v2 + b0, v3 + b1);
            } else {  // MODE 5
                const int bb = z >> 4, hh = z & (H - 1);
                const int dd = wn * WN + nf * 8 + cq;
                *(float2*)(g_ctx + ((size_t)(bb * S + row0)) * E + hh * D + dd) =
                    make_float2(v0 * inv0, v1 * inv0);
                *(float2*)(g_ctx + ((size_t)(bb * S + row1)) * E + hh * D + dd) =
                    make_float2(v2 * inv1, v3 * inv1);
            }
        }
    }
}

// ---------------------------------------------------------------------------
// mean over heads + rowinv: out2[b,q,k] = sum_h expS[b,h,q,k]/(rowsum_h * H)
// ---------------------------------------------------------------------------
__global__ __launch_bounds__(256)
void mean_kernel(float* __restrict__ out2)
{
    const int r = blockIdx.x;                  // 0..BS-1
    const int b = r >> 11, q = r & (S - 1);
    const int tid = threadIdx.x;

    __shared__ float inv[H];
    if (tid < H) {
        const float4* ps = (const float4*)(g_psum + ((size_t)(b * H + tid) * S + q) * 32);
        float s = 0.f;
        #pragma unroll
        for (int i = 0; i < 8; i++) {
            float4 t = ps[i];
            s += (t.x + t.y) + (t.z + t.w);
        }
        const float ri = 1.0f / s;
        g_rowinv[(size_t)(b * H + tid) * S + q] = ri;
        inv[tid] = ri * (1.0f / (float)H);
    }
    __syncthreads();

    float acc[8] = {0.f, 0.f, 0.f, 0.f, 0.f, 0.f, 0.f, 0.f};
    #pragma unroll
    for (int h = 0; h < H; h++) {
        const uint4 t = *(const uint4*)((const char*)g_expS +
            ((size_t)(b * H + h) * S + q) * (S * 2) + tid * 16);
        const float iv = inv[h];
        const __half2* hp = (const __half2*)&t;
        #pragma unroll
        for (int j = 0; j < 4; j++) {
            float2 f = __half22float2(hp[j]);
            acc[2 * j]     += f.x * iv;
            acc[2 * j + 1] += f.y * iv;
        }
    }
    float* o = out2 + (size_t)r * S + tid * 8;
    *(float4*)o       = make_float4(acc[0], acc[1], acc[2], acc[3]);
    *(float4*)(o + 4) = make_float4(acc[4], acc[5], acc[6], acc[7]);
}

// ---------------------------------------------------------------------------
// Launch
// ---------------------------------------------------------------------------
extern "C" void kernel_launch(void* const* d_in, const int* in_sizes, int n_in,
                              void* d_out, int out_size)
{
    const float* query = (const float*)d_in[0];
    const float* key   = (const float*)d_in[1];
    const float* value = (const float*)d_in[2];
    const float* Wq = (const float*)d_in[3];
    const float* bq = (const float*)d_in[4];
    const float* Wk = (const float*)d_in[5];
    const float* bk = (const float*)d_in[6];
    const float* Wv = (const float*)d_in[7];
    const float* bv = (const float*)d_in[8];
    const float* Wo = (const float*)d_in[9];
    const float* bo = (const float*)d_in[10];

    float* out       = (float*)d_out;
    float* attn_mean = out + (size_t)BS * E;

    cudaFuncSetAttribute(mm_gemm<0>, cudaFuncAttributeMaxDynamicSharedMemorySize, SM_TOTAL);
    cudaFuncSetAttribute(mm_gemm<1>, cudaFuncAttributeMaxDynamicSharedMemorySize, SM_TOTAL);
    cudaFuncSetAttribute(mm_gemm<2>, cudaFuncAttributeMaxDynamicSharedMemorySize, SM_TOTAL);
    cudaFuncSetAttribute(mm_gemm<3>, cudaFuncAttributeMaxDynamicSharedMemorySize, SM_TOTAL);
    cudaFuncSetAttribute(mm_gemm<5>, cudaFuncAttributeMaxDynamicSharedMemorySize, SM_TOTAL);
    cudaFuncSetAttribute(scores_k,   cudaFuncAttributeMaxDynamicSharedMemorySize, SC_SMEM);

    const dim3 projGrid(E / 128, BS / 128);                 // (8, 64)
    mm_gemm<0><<<projGrid, 256, SM_TOTAL>>>(query, Wq, bq, nullptr);
    mm_gemm<1><<<projGrid, 256, SM_TOTAL>>>(key,   Wk, bk, nullptr);
    mm_gemm<2><<<projGrid, 256, SM_TOTAL>>>(value, Wv, bv, nullptr);

    scores_k<<<dim3(S / 128, S / 128, BH), 256, SC_SMEM>>>();

    mean_kernel<<<BS, 256>>>(attn_mean);

    mm_gemm<5><<<dim3(1, S / 128, BH), 256, SM_TOTAL>>>(nullptr, nullptr, nullptr, nullptr);

    mm_gemm<3><<<projGrid, 256, SM_TOTAL>>>(nullptr, Wo, bo, out);
}

// round 14
// speedup vs baseline: 3.4085x; 1.1120x over previous
#include <cuda_runtime.h>
#include <cuda_bf16.h>
#include <cuda_fp16.h>
#include <cstdint>
#include <cstddef>

// Problem constants
static constexpr int B  = 4;
static constexpr int S  = 2048;
static constexpr int E  = 1024;
static constexpr int H  = 16;
static constexpr int D  = 64;
static constexpr int BS = B * S;    // 8192
static constexpr int BH = B * H;    // 64

// ---------------------------------------------------------------------------
// Scratch
// ---------------------------------------------------------------------------
__device__ uint32_t g_Qh  [(size_t)BH * S * 32];  // [z,s,d/2] bf16x2 hi (Q/8)
__device__ uint32_t g_Ql  [(size_t)BH * S * 32];  // [z,s,d/2] bf16x2 lo
__device__ uint32_t g_Kh  [(size_t)BH * S * 32];
__device__ uint32_t g_Kl  [(size_t)BH * S * 32];
__device__ float    g_Vt  [(size_t)BH * D * S];   // [z,d,s]
__device__ float    g_ctx [(size_t)BS * E];       // [b,s,e]
__device__ __half   g_expS[(size_t)BH * S * S];   // [z,q,k] unnormalized exp
__device__ float    g_psum[(size_t)BH * S * 32];  // [z,q,32] row partial sums
__device__ float    g_rowinv[(size_t)BH * S];     // [z,q] 1/rowsum

// ---------------------------------------------------------------------------
// Helpers
// ---------------------------------------------------------------------------
__device__ __forceinline__ uint32_t smem_u32(const void* p) {
    uint32_t a;
    asm("{ .reg .u64 t; cvta.to.shared.u64 t, %1; cvt.u32.u64 %0, t; }" : "=r"(a) : "l"(p));
    return a;
}
// pack two fp32 -> bf16x2, e0 in low half
__device__ __forceinline__ uint32_t cvt2(float e0, float e1) {
    uint32_t r;
    asm("cvt.rn.bf16x2.f32 %0, %1, %2;" : "=r"(r) : "f"(e1), "f"(e0));
    return r;
}
__device__ __forceinline__ void pack2(float v0, float v1, uint32_t& hi, uint32_t& lo) {
    hi = cvt2(v0, v1);
    float f0 = __uint_as_float(hi << 16), f1 = __uint_as_float(hi & 0xFFFF0000u);
    lo = cvt2(v0 - f0, v1 - f1);
}
__device__ __forceinline__ void pack_hilo_bf(float4 v, uint2& hi, uint2& lo) {
    pack2(v.x, v.y, hi.x, lo.x);
    pack2(v.z, v.w, hi.y, lo.y);
}
__device__ __forceinline__ void pack_hilo_h(float4 v, uint2& hi, uint2& lo) {
    __half2 h01 = __floats2half2_rn(v.x, v.y);
    __half2 h23 = __floats2half2_rn(v.z, v.w);
    float2 f01 = __half22float2(h01), f23 = __half22float2(h23);
    __half2 l01 = __floats2half2_rn(v.x - f01.x, v.y - f01.y);
    __half2 l23 = __floats2half2_rn(v.z - f23.x, v.w - f23.y);
    hi = make_uint2(*(uint32_t*)&h01, *(uint32_t*)&h23);
    lo = make_uint2(*(uint32_t*)&l01, *(uint32_t*)&l23);
}
#define LDSM_X4(r0, r1, r2, r3, addr) \
    asm volatile("ldmatrix.sync.aligned.m8n8.x4.shared.b16 {%0,%1,%2,%3}, [%4];" \
        : "=r"(r0), "=r"(r1), "=r"(r2), "=r"(r3) : "r"(addr))

__device__ __forceinline__ void mma_bf16(float* d, const uint32_t* a, const uint32_t* b) {
    asm volatile(
        "mma.sync.aligned.m16n8k16.row.col.f32.bf16.bf16.f32 "
        "{%0,%1,%2,%3}, {%4,%5,%6,%7}, {%8,%9}, {%0,%1,%2,%3};"
        : "+f"(d[0]), "+f"(d[1]), "+f"(d[2]), "+f"(d[3])
        : "r"(a[0]), "r"(a[1]), "r"(a[2]), "r"(a[3]), "r"(b[0]), "r"(b[1]));
}
__device__ __forceinline__ void mma_f16(float* d, const uint32_t* a, const uint32_t* b) {
    asm volatile(
        "mma.sync.aligned.m16n8k16.row.col.f32.f16.f16.f32 "
        "{%0,%1,%2,%3}, {%4,%5,%6,%7}, {%8,%9}, {%0,%1,%2,%3};"
        : "+f"(d[0]), "+f"(d[1]), "+f"(d[2]), "+f"(d[3])
        : "r"(a[0]), "r"(a[1]), "r"(a[2]), "r"(a[3]), "r"(b[0]), "r"(b[1]));
}

// ---------------------------------------------------------------------------
// Scores kernel: expS[z,q,k] = exp(Qs . K)  (Q pre-scaled by 1/8)
// 128x128 CTA tile, 8 warps (4m x 2n).  Operands pre-split bf16 hi/lo.
// K=64 staged fully up-front.  Epilogue REUSES operand smem as the fp16
// staging tile (operands dead after the MMAs) -> 80 KiB total -> 2 CTAs/SM.
// ---------------------------------------------------------------------------
static constexpr int SC_SMEM = 81920;

__global__ __launch_bounds__(256, 2)
void scores_k()
{
    extern __shared__ char smem[];
    const uint32_t sb = smem_u32(smem);
    const int tid = threadIdx.x, wid = tid >> 5, l = tid & 31;
    const int wm = wid >> 1, wn = wid & 1;
    const int bn = blockIdx.x, bm = blockIdx.y, z = blockIdx.z;

    // ---- stage operands: raw 16B copies, no conversion ----
    {
        const int row = tid >> 1, c = tid & 1;   // chunk c = k block [c*32, c*32+32)
        const uint4* qh = (const uint4*)(g_Qh + ((size_t)z * S + bm * 128 + row) * 32) + c * 4;
        const uint4* ql = (const uint4*)(g_Ql + ((size_t)z * S + bm * 128 + row) * 32) + c * 4;
        const uint4* kh = (const uint4*)(g_Kh + ((size_t)z * S + bn * 128 + row) * 32) + c * 4;
        const uint4* kl = (const uint4*)(g_Kl + ((size_t)z * S + bn * 128 + row) * 32) + c * 4;
        char* dq = smem + c * 10240 + row * 80;
        #pragma unroll
        for (int j = 0; j < 4; j++) *(uint4*)(dq + j * 16)         = qh[j];
        #pragma unroll
        for (int j = 0; j < 4; j++) *(uint4*)(dq + 20480 + j * 16) = ql[j];
        #pragma unroll
        for (int j = 0; j < 4; j++) *(uint4*)(dq + 40960 + j * 16) = kh[j];
        #pragma unroll
        for (int j = 0; j < 4; j++) *(uint4*)(dq + 61440 + j * 16) = kl[j];
    }
    __syncthreads();

    const int aRowSel = ((l >> 3) & 1) * 8 + (l & 7);
    const int aKsel   = ((l >> 4) & 1) * 16;
    const int bRowSel = ((l >> 4) & 1) * 8 + (l & 7);
    const int bKsel   = ((l >> 3) & 1) * 16;

    float dacc[2][8][4];
    #pragma unroll
    for (int mf = 0; mf < 2; mf++)
        #pragma unroll
        for (int nf = 0; nf < 8; nf++)
            #pragma unroll
            for (int u = 0; u < 4; u++) dacc[mf][nf][u] = 0.f;

    #pragma unroll
    for (int c = 0; c < 2; c++) {
        #pragma unroll
        for (int s = 0; s < 2; s++) {
            uint32_t af[2][2][4];
            #pragma unroll
            for (int mf = 0; mf < 2; mf++)
                #pragma unroll
                for (int hl = 0; hl < 2; hl++) {
                    const uint32_t ad = sb + hl * 20480 + c * 10240 +
                        (wm * 32 + mf * 16 + aRowSel) * 80 + s * 32 + aKsel;
                    LDSM_X4(af[mf][hl][0], af[mf][hl][1], af[mf][hl][2], af[mf][hl][3], ad);
                }
            uint32_t bf[8][2][2];
            #pragma unroll
            for (int np = 0; np < 4; np++)
                #pragma unroll
                for (int hl = 0; hl < 2; hl++) {
                    uint32_t r0, r1, r2, r3;
                    const uint32_t bd = sb + 40960 + hl * 20480 + c * 10240 +
                        (wn * 64 + np * 16 + bRowSel) * 80 + s * 32 + bKsel;
                    LDSM_X4(r0, r1, r2, r3, bd);
                    bf[2 * np][hl][0] = r0; bf[2 * np][hl][1] = r1;
                    bf[2 * np + 1][hl][0] = r2; bf[2 * np + 1][hl][1] = r3;
                }
            #pragma unroll
            for (int mf = 0; mf < 2; mf++)
                #pragma unroll
                for (int nf = 0; nf < 8; nf++) {
                    mma_bf16(dacc[mf][nf], af[mf][0], bf[nf][0]);   // hi*hi
                    mma_bf16(dacc[mf][nf], af[mf][1], bf[nf][0]);   // lo*hi
                    mma_bf16(dacc[mf][nf], af[mf][0], bf[nf][1]);   // hi*lo
                }
        }
    }

    // all ldmatrix reads done in every warp before staging overwrites operands
    __syncthreads();

    // ---- epilogue: exp -> swizzled staging (reused smem), partial rowsums ----
    const int g = l >> 2;

    #pragma unroll
    for (int mf = 0; mf < 2; mf++) {
        const int row0 = bm * 128 + wm * 32 + mf * 16 + g;
        const int row1 = row0 + 8;
        float rs0 = 0.f, rs1 = 0.f;
        #pragma unroll
        for (int nf = 0; nf < 8; nf++) {
            const float e0 = __expf(dacc[mf][nf][0]), e1 = __expf(dacc[mf][nf][1]);
            const float e2 = __expf(dacc[mf][nf][2]), e3 = __expf(dacc[mf][nf][3]);
            rs0 += e0 + e1; rs1 += e2 + e3;
            __half2 p01 = __floats2half2_rn(e0, e1);
            __half2 p23 = __floats2half2_rn(e2, e3);
            const int srow0 = wm * 32 + mf * 16 + g;
            const int srow1 = srow0 + 8;
            const int chunk = wn * 8 + nf;          // 16B chunk index
            *(__half2*)(smem + srow0 * 256 +
                        ((chunk ^ (srow0 & 15)) * 16) + (l & 3) * 4) = p01;
            *(__half2*)(smem + srow1 * 256 +
                        ((chunk ^ (srow1 & 15)) * 16) + (l & 3) * 4) = p23;
        }
        rs0 += __shfl_xor_sync(0xffffffffu, rs0, 1);
        rs0 += __shfl_xor_sync(0xffffffffu, rs0, 2);
        rs1 += __shfl_xor_sync(0xffffffffu, rs1, 1);
        rs1 += __shfl_xor_sync(0xffffffffu, rs1, 2);
        if ((l & 3) == 0) {
            const int slot = bn * 2 + wn;
            g_psum[((size_t)z * S + row0) * 32 + slot] = rs0;
            g_psum[((size_t)z * S + row1) * 32 + slot] = rs1;
        }
    }
    __syncthreads();

    // ---- coalesced copy-out (conflict-free via swizzle) ----
    {
        const int j = tid & 15, rowbase = tid >> 4;
        #pragma unroll
        for (int i = 0; i < 8; i++) {
            const int row = rowbase + 16 * i;
            const uint4 v = *(const uint4*)(smem + row * 256 + ((j ^ (row & 15)) * 16));
            *(uint4*)((char*)g_expS + ((size_t)z * S + bm * 128 + row) * (S * 2) +
                      bn * 256 + j * 16) = v;
        }
    }
}

// ---------------------------------------------------------------------------
// Generic split-precision mma.sync GEMM.  C = A[M,K] @ Bmat[N,K]^T (k-major).
// MODE 0/1/2: Q/K/V projection (bf16x3).  MODE 3: O projection (bf16x3).
// MODE 5: ctx = normalized attn @ V (A exact fp16, V fp16 hi/lo -> 2 MMAs),
//         2 CTAs/SM (small tile, low regs, 60 KiB smem).
// ---------------------------------------------------------------------------
static constexpr int A_SZ = 128 * 80;
static constexpr int SM_TOTAL  = 4 * A_SZ + 4 * (128 * 80);  // 81920 (modes 0-3)
static constexpr int SM_MODE5  = 4 * A_SZ + 4 * (64 * 80);   // 61440

template <int MODE>
__global__ __launch_bounds__(256, (MODE == 5) ? 2 : 1)
void mm_gemm(const float* __restrict__ Ain, const float* __restrict__ Bin,
             const float* __restrict__ bias, float* __restrict__ Cout)
{
    constexpr int NTILE = (MODE == 5) ? 64 : 128;
    constexpr int NC    = (MODE == 5) ? 64 : 32;
    constexpr int LDA   = (MODE == 5) ? 2048 : 1024;
    constexpr int LDB   = (MODE == 5) ? 2048 : 1024;
    constexpr int WN    = NTILE / 2;
    constexpr int NF    = WN / 8;
    constexpr int B_SZ  = NTILE * 80;
    constexpr int OFFB0 = 4 * A_SZ;

    extern __shared__ char smem[];
    const uint32_t sb = smem_u32(smem);
    const int tid = threadIdx.x, wid = tid >> 5, l = tid & 31;
    const int wm = wid >> 1, wn = wid & 1;
    const int bn = blockIdx.x, bm = blockIdx.y;
    const int z  = (MODE == 5) ? blockIdx.z : 0;

    const float* Abase = nullptr;
    const float* Bbase;
    if constexpr (MODE == 5)      { Bbase = g_Vt + (size_t)z * D * S; }
    else if constexpr (MODE == 3) { Abase = g_ctx; Bbase = Bin; }
    else                          { Abase = Ain;   Bbase = Bin; }

    const int arow = tid >> 1, acol = (tid & 1) * 16;
    const int browL = (NTILE == 128) ? (tid >> 1) : (tid >> 2);
    const int bcolL = (NTILE == 128) ? (tid & 1) * 16 : (tid & 3) * 8;
    constexpr int NBL = (NTILE == 128) ? 4 : 2;

    const float* aG = (MODE == 5) ? nullptr : (Abase + (size_t)(bm * 128 + arow) * LDA + acol);
    const float* bG = Bbase + (size_t)(bn * NTILE + browL) * LDB + bcolL;
    const __half* aGh = nullptr;
    if constexpr (MODE == 5)
        aGh = g_expS + (size_t)z * S * S + (size_t)(bm * 128 + arow) * S + (tid & 1) * 16;

    const int aRowSel = ((l >> 3) & 1) * 8 + (l & 7);
    const int aKsel   = ((l >> 4) & 1) * 16;
    const int bRowSel = ((l >> 4) & 1) * 8 + (l & 7);
    const int bKsel   = ((l >> 3) & 1) * 16;

    float dacc[2][NF][4];
    #pragma unroll
    for (int mf = 0; mf < 2; mf++)
        #pragma unroll
        for (int nf = 0; nf < NF; nf++)
            #pragma unroll
            for (int u = 0; u < 4; u++) dacc[mf][nf][u] = 0.f;

    float4 aR[4], bR[NBL];
    uint4  aRh[2];
    if constexpr (MODE == 5) {
        #pragma unroll
        for (int i = 0; i < 2; i++) aRh[i] = *(const uint4*)(aGh + 8 * i);
    } else {
        #pragma unroll
        for (int i = 0; i < 4; i++) aR[i] = *(const float4*)(aG + 4 * i);
    }
    #pragma unroll
    for (int i = 0; i < NBL; i++) bR[i] = *(const float4*)(bG + 4 * i);

    // stage chunk 0
    {
        if constexpr (MODE == 5) {
            #pragma unroll
            for (int i = 0; i < 2; i++)
                *(uint4*)(smem + arow * 80 + (tid & 1) * 32 + 16 * i) = aRh[i];
        } else {
            #pragma unroll
            for (int i = 0; i < 4; i++) {
                uint2 hi, lo; pack_hilo_bf(aR[i], hi, lo);
                const int off = arow * 80 + (acol + 4 * i) * 2;
                *(uint2*)(smem + off)        = hi;
                *(uint2*)(smem + A_SZ + off) = lo;
            }
        }
        #pragma unroll
        for (int i = 0; i < NBL; i++) {
            uint2 hi, lo;
            if constexpr (MODE == 5) pack_hilo_h(bR[i], hi, lo);
            else                     pack_hilo_bf(bR[i], hi, lo);
            const int off = browL * 80 + (bcolL + 4 * i) * 2;
            *(uint2*)(smem + OFFB0 + off)        = hi;
            *(uint2*)(smem + OFFB0 + B_SZ + off) = lo;
        }
    }
    __syncthreads();

    for (int c = 0; c < NC; c++) {
        const int buf = c & 1;
        if (c + 1 < NC) {
            if constexpr (MODE == 5) {
                #pragma unroll
                for (int i = 0; i < 2; i++) aRh[i] = *(const uint4*)(aGh + (c + 1) * 32 + 8 * i);
            } else {
                #pragma unroll
                for (int i = 0; i < 4; i++) aR[i] = *(const float4*)(aG + (c + 1) * 32 + 4 * i);
            }
            #pragma unroll
            for (int i = 0; i < NBL; i++) bR[i] = *(const float4*)(bG + (c + 1) * 32 + 4 * i);
        }

        const uint32_t aB = sb + buf * 2 * A_SZ;
        const uint32_t bB = sb + OFFB0 + buf * 2 * B_SZ;

        #pragma unroll
        for (int s = 0; s < 2; s++) {
            if constexpr (MODE == 5) {
                uint32_t af[2][4];
                #pragma unroll
                for (int mf = 0; mf < 2; mf++) {
                    const uint32_t ad = aB + (wm * 32 + mf * 16 + aRowSel) * 80 + s * 32 + aKsel;
                    LDSM_X4(af[mf][0], af[mf][1], af[mf][2], af[mf][3], ad);
                }
                uint32_t bf[NF][2][2];
                #pragma unroll
                for (int np = 0; np < NF / 2; np++)
                    #pragma unroll
                    for (int hl = 0; hl < 2; hl++) {
                        uint32_t r0, r1, r2, r3;
                        const uint32_t bd = bB + hl * B_SZ +
                            (wn * WN + np * 16 + bRowSel) * 80 + s * 32 + bKsel;
                        LDSM_X4(r0, r1, r2, r3, bd);
                        bf[2 * np][hl][0] = r0; bf[2 * np][hl][1] = r1;
                        bf[2 * np + 1][hl][0] = r2; bf[2 * np + 1][hl][1] = r3;
                    }
                #pragma unroll
                for (int mf = 0; mf < 2; mf++)
                    #pragma unroll
                    for (int nf = 0; nf < NF; nf++) {
                        mma_f16(dacc[mf][nf], af[mf], bf[nf][0]);
                        mma_f16(dacc[mf][nf], af[mf], bf[nf][1]);
                    }
            } else {
                uint32_t af[2][2][4];
                #pragma unroll
                for (int mf = 0; mf < 2; mf++)
                    #pragma unroll
                    for (int hl = 0; hl < 2; hl++) {
                        const uint32_t ad = aB + hl * A_SZ +
                            (wm * 32 + mf * 16 + aRowSel) * 80 + s * 32 + aKsel;
                        LDSM_X4(af[mf][hl][0], af[mf][hl][1], af[mf][hl][2], af[mf][hl][3], ad);
                    }
                uint32_t bf[NF][2][2];
                #pragma unroll
                for (int np = 0; np < NF / 2; np++)
                    #pragma unroll
                    for (int hl = 0; hl < 2; hl++) {
                        uint32_t r0, r1, r2, r3;
                        const uint32_t bd = bB + hl * B_SZ +
                            (wn * WN + np * 16 + bRowSel) * 80 + s * 32 + bKsel;
                        LDSM_X4(r0, r1, r2, r3, bd);
                        bf[2 * np][hl][0] = r0; bf[2 * np][hl][1] = r1;
                        bf[2 * np + 1][hl][0] = r2; bf[2 * np + 1][hl][1] = r3;
                    }
                #pragma unroll
                for (int mf = 0; mf < 2; mf++)
                    #pragma unroll
                    for (int nf = 0; nf < NF; nf++) {
                        mma_bf16(dacc[mf][nf], af[mf][0], bf[nf][0]);
                        mma_bf16(dacc[mf][nf], af[mf][1], bf[nf][0]);
                        mma_bf16(dacc[mf][nf], af[mf][0], bf[nf][1]);
                    }
            }
        }

        if (c + 1 < NC) {
            __syncthreads();
            const int nb = (c + 1) & 1;
            if constexpr (MODE == 5) {
                #pragma unroll
                for (int i = 0; i < 2; i++)
                    *(uint4*)(smem + nb * 2 * A_SZ + arow * 80 + (tid & 1) * 32 + 16 * i) = aRh[i];
            } else {
                #pragma unroll
                for (int i = 0; i < 4; i++) {
                    uint2 hi, lo; pack_hilo_bf(aR[i], hi, lo);
                    const int off = nb * 2 * A_SZ + arow * 80 + (acol + 4 * i) * 2;
                    *(uint2*)(smem + off)        = hi;
                    *(uint2*)(smem + A_SZ + off) = lo;
                }
            }
            #pragma unroll
            for (int i = 0; i < NBL; i++) {
                uint2 hi, lo;
                if constexpr (MODE == 5) pack_hilo_h(bR[i], hi, lo);
                else                     pack_hilo_bf(bR[i], hi, lo);
                const int off = OFFB0 + nb * 2 * B_SZ + browL * 80 + (bcolL + 4 * i) * 2;
                *(uint2*)(smem + off)        = hi;
                *(uint2*)(smem + B_SZ + off) = lo;
            }
            __syncthreads();
        }
    }

    // ------------------------- epilogue -------------------------
    const int g  = l >> 2;
    const int cq = (l & 3) * 2;

    #pragma unroll
    for (int mf = 0; mf < 2; mf++) {
        const int row0 = bm * 128 + wm * 32 + mf * 16 + g;
        const int row1 = row0 + 8;
        float inv0 = 1.f, inv1 = 1.f;
        if constexpr (MODE == 5) {
            inv0 = g_rowinv[(size_t)z * S + row0];
            inv1 = g_rowinv[(size_t)z * S + row1];
        }
        #pragma unroll
        for (int nf = 0; nf < NF; nf++) {
            const int gcol = bn * NTILE + wn * WN + nf * 8 + cq;
            float v0 = dacc[mf][nf][0], v1 = dacc[mf][nf][1];
            float v2 = dacc[mf][nf][2], v3 = dacc[mf][nf][3];

            if constexpr (MODE <= 2) {
                const float b0 = __ldg(bias + gcol), b1 = __ldg(bias + gcol + 1);
                v0 += b0; v1 += b1; v2 += b0; v3 += b1;
                if (MODE == 0) { v0 *= 0.125f; v1 *= 0.125f; v2 *= 0.125f; v3 *= 0.125f; }
                const int hh = gcol >> 6, dd = gcol & 63;
                const int bb0 = row0 >> 11, ss0 = row0 & (S - 1);
                const int bb1 = row1 >> 11, ss1 = row1 & (S - 1);
                if constexpr (MODE == 0 || MODE == 1) {
                    uint32_t hi0, lo0, hi1, lo1;
                    pack2(v0, v1, hi0, lo0);
                    pack2(v2, v3, hi1, lo1);
                    const size_t i0 = ((size_t)(bb0 * H + hh) * S + ss0) * 32 + (dd >> 1);
                    const size_t i1 = ((size_t)(bb1 * H + hh) * S + ss1) * 32 + (dd >> 1);
                    if constexpr (MODE == 0) {
                        g_Qh[i0] = hi0; g_Ql[i0] = lo0;
                        g_Qh[i1] = hi1; g_Ql[i1] = lo1;
                    } else {
                        g_Kh[i0] = hi0; g_Kl[i0] = lo0;
                        g_Kh[i1] = hi1; g_Kl[i1] = lo1;
                    }
                } else {
                    float* vt0 = g_Vt + (((size_t)(bb0 * H + hh)) * D + dd) * S + ss0;
                    float* vt1 = g_Vt + (((size_t)(bb1 * H + hh)) * D + dd) * S + ss1;
                    vt0[0] = v0; vt0[S] = v1;
                    vt1[0] = v2; vt1[S] = v3;
                }
            } else if constexpr (MODE == 3) {
                const float b0 = __ldg(bias + gcol), b1 = __ldg(bias + gcol + 1);
                *(float2*)(Cout + (size_t)row0 * E + gcol) = make_float2(v0 + b0, v1 + b1);
                *(float2*)(Cout + (size_t)row1 * E + gcol) = make_float2(v2 + b0, v3 + b1);
            } else {  // MODE 5
                const int bb = z >> 4, hh = z & (H - 1);
                const int dd = wn * WN + nf * 8 + cq;
                *(float2*)(g_ctx + ((size_t)(bb * S + row0)) * E + hh * D + dd) =
                    make_float2(v0 * inv0, v1 * inv0);
                *(float2*)(g_ctx + ((size_t)(bb * S + row1)) * E + hh * D + dd) =
                    make_float2(v2 * inv1, v3 * inv1);
            }
        }
    }
}

// ---------------------------------------------------------------------------
// mean over heads + rowinv: out2[b,q,k] = sum_h expS[b,h,q,k]/(rowsum_h * H)
// ---------------------------------------------------------------------------
__global__ __launch_bounds__(256)
void mean_kernel(float* __restrict__ out2)
{
    const int r = blockIdx.x;                  // 0..BS-1
    const int b = r >> 11, q = r & (S - 1);
    const int tid = threadIdx.x;

    __shared__ float inv[H];
    if (tid < H) {
        const float4* ps = (const float4*)(g_psum + ((size_t)(b * H + tid) * S + q) * 32);
        float s = 0.f;
        #pragma unroll
        for (int i = 0; i < 8; i++) {
            float4 t = ps[i];
            s += (t.x + t.y) + (t.z + t.w);
        }
        const float ri = 1.0f / s;
        g_rowinv[(size_t)(b * H + tid) * S + q] = ri;
        inv[tid] = ri * (1.0f / (float)H);
    }
    __syncthreads();

    float acc[8] = {0.f, 0.f, 0.f, 0.f, 0.f, 0.f, 0.f, 0.f};
    #pragma unroll
    for (int h = 0; h < H; h++) {
        const uint4 t = *(const uint4*)((const char*)g_expS +
            ((size_t)(b * H + h) * S + q) * (S * 2) + tid * 16);
        const float iv = inv[h];
        const __half2* hp = (const __half2*)&t;
        #pragma unroll
        for (int j = 0; j < 4; j++) {
            float2 f = __half22float2(hp[j]);
            acc[2 * j]     += f.x * iv;
            acc[2 * j + 1] += f.y * iv;
        }
    }
    float* o = out2 + (size_t)r * S + tid * 8;
    *(float4*)o       = make_float4(acc[0], acc[1], acc[2], acc[3]);
    *(float4*)(o + 4) = make_float4(acc[4], acc[5], acc[6], acc[7]);
}

// ---------------------------------------------------------------------------
// Launch
// ---------------------------------------------------------------------------
extern "C" void kernel_launch(void* const* d_in, const int* in_sizes, int n_in,
                              void* d_out, int out_size)
{
    const float* query = (const float*)d_in[0];
    const float* key   = (const float*)d_in[1];
    const float* value = (const float*)d_in[2];
    const float* Wq = (const float*)d_in[3];
    const float* bq = (const float*)d_in[4];
    const float* Wk = (const float*)d_in[5];
    const float* bk = (const float*)d_in[6];
    const float* Wv = (const float*)d_in[7];
    const float* bv = (const float*)d_in[8];
    const float* Wo = (const float*)d_in[9];
    const float* bo = (const float*)d_in[10];

    float* out       = (float*)d_out;
    float* attn_mean = out + (size_t)BS * E;

    cudaFuncSetAttribute(mm_gemm<0>, cudaFuncAttributeMaxDynamicSharedMemorySize, SM_TOTAL);
    cudaFuncSetAttribute(mm_gemm<1>, cudaFuncAttributeMaxDynamicSharedMemorySize, SM_TOTAL);
    cudaFuncSetAttribute(mm_gemm<2>, cudaFuncAttributeMaxDynamicSharedMemorySize, SM_TOTAL);
    cudaFuncSetAttribute(mm_gemm<3>, cudaFuncAttributeMaxDynamicSharedMemorySize, SM_TOTAL);
    cudaFuncSetAttribute(mm_gemm<5>, cudaFuncAttributeMaxDynamicSharedMemorySize, SM_MODE5);
    cudaFuncSetAttribute(scores_k,   cudaFuncAttributeMaxDynamicSharedMemorySize, SC_SMEM);

    const dim3 projGrid(E / 128, BS / 128);                 // (8, 64)
    mm_gemm<0><<<projGrid, 256, SM_TOTAL>>>(query, Wq, bq, nullptr);
    mm_gemm<1><<<projGrid, 256, SM_TOTAL>>>(key,   Wk, bk, nullptr);
    mm_gemm<2><<<projGrid, 256, SM_TOTAL>>>(value, Wv, bv, nullptr);

    scores_k<<<dim3(S / 128, S / 128, BH), 256, SC_SMEM>>>();

    mean_kernel<<<BS, 256>>>(attn_mean);

    mm_gemm<5><<<dim3(1, S / 128, BH), 256, SM_MODE5>>>(nullptr, nullptr, nullptr, nullptr);

    mm_gemm<3><<<projGrid, 256, SM_TOTAL>>>(nullptr, Wo, bo, out);
}